// round 2
// baseline (speedup 1.0000x reference)
#include <cuda_runtime.h>
#include <cuda_bf16.h>
#include <cstdint>
#include <cstddef>

// Problem constants (fixed by the dataset)
#define NN   100000
#define FEAT 256
#define HID  128
#define OUTF 64
#define EE   1600000

// ---------------------------------------------------------------------------
// Static device scratch (allocation-free rule: __device__ globals)
// ---------------------------------------------------------------------------
__device__ __align__(16) float g_bufA[(size_t)NN * HID];   // 51.2 MB
__device__ __align__(16) float g_bufB[(size_t)NN * HID];   // 51.2 MB
__device__ __align__(16) float g_bufC[(size_t)NN * OUTF];  // 25.6 MB
__device__ __align__(16) float g_dinv[NN];
__device__ __align__(16) float g_norm[EE];
__device__ __align__(16) int   g_deg[NN];

// ---------------------------------------------------------------------------
// Prep kernels: degree, dinv, per-edge norm
// edge_index is int32 (JAX x64 disabled -> int64 request silently becomes int32)
// ---------------------------------------------------------------------------
__global__ void k_deg_init(int* deg, int n) {
    int i = blockIdx.x * blockDim.x + threadIdx.x;
    if (i < n) deg[i] = 1;  // self-loop
}

__global__ void k_deg_count(const int* __restrict__ ei, int* deg, int e_cnt) {
    int e = blockIdx.x * blockDim.x + threadIdx.x;
    if (e < e_cnt) atomicAdd(deg + ei[e_cnt + e], 1);
}

__global__ void k_dinv(const int* __restrict__ deg, float* dinv, int n) {
    int i = blockIdx.x * blockDim.x + threadIdx.x;
    if (i < n) dinv[i] = rsqrtf((float)deg[i]);
}

__global__ void k_norm(const int* __restrict__ ei, const float* __restrict__ dinv,
                       float* nrm, int e_cnt) {
    int e = blockIdx.x * blockDim.x + threadIdx.x;
    if (e < e_cnt) {
        int s = ei[e];
        int d = ei[e_cnt + e];
        nrm[e] = __ldg(dinv + s) * __ldg(dinv + d);
    }
}

// ---------------------------------------------------------------------------
// SGEMM: C[M,BN] = A[M,K] @ W[K,BN], fp32, 128-row tiles, register blocking
// ---------------------------------------------------------------------------
template <int BK, int BN, int TM, int TN>
__global__ void gemm_kernel(const float* __restrict__ A, const float* __restrict__ W,
                            float* __restrict__ C, int M, int K) {
    constexpr int BM  = 128;
    constexpr int NTH = (BM / TM) * (BN / TN);  // 256 for both configs
    __shared__ float As[BK][BM + 4];
    __shared__ float Ws[BK][BN];

    const int tid = threadIdx.x;
    const int m0  = blockIdx.x * BM;
    const int tx  = tid % (BN / TN);
    const int ty  = tid / (BN / TN);

    float acc[TM][TN];
#pragma unroll
    for (int i = 0; i < TM; i++)
#pragma unroll
        for (int j = 0; j < TN; j++) acc[i][j] = 0.0f;

    for (int k0 = 0; k0 < K; k0 += BK) {
        // Load A tile (BM x BK), store transposed into As[k][row]
#pragma unroll
        for (int i = tid; i < BM * (BK / 4); i += NTH) {
            int r  = i / (BK / 4);
            int c4 = i % (BK / 4);
            float4 v = make_float4(0.f, 0.f, 0.f, 0.f);
            if (m0 + r < M)
                v = *reinterpret_cast<const float4*>(A + (size_t)(m0 + r) * K + k0 + c4 * 4);
            As[c4 * 4 + 0][r] = v.x;
            As[c4 * 4 + 1][r] = v.y;
            As[c4 * 4 + 2][r] = v.z;
            As[c4 * 4 + 3][r] = v.w;
        }
        // Load W tile (BK x BN)
#pragma unroll
        for (int i = tid; i < BK * (BN / 4); i += NTH) {
            int r  = i / (BN / 4);
            int c4 = i % (BN / 4);
            *reinterpret_cast<float4*>(&Ws[r][c4 * 4]) =
                *reinterpret_cast<const float4*>(W + (size_t)(k0 + r) * BN + c4 * 4);
        }
        __syncthreads();

#pragma unroll
        for (int k = 0; k < BK; k++) {
            float a[TM], b[TN];
#pragma unroll
            for (int i = 0; i < TM; i++) a[i] = As[k][ty * TM + i];
#pragma unroll
            for (int j = 0; j < TN; j++) b[j] = Ws[k][tx * TN + j];
#pragma unroll
            for (int i = 0; i < TM; i++)
#pragma unroll
                for (int j = 0; j < TN; j++) acc[i][j] = fmaf(a[i], b[j], acc[i][j]);
        }
        __syncthreads();
    }

#pragma unroll
    for (int i = 0; i < TM; i++) {
        int row = m0 + ty * TM + i;
        if (row < M) {
#pragma unroll
            for (int j4 = 0; j4 < TN / 4; j4++) {
                float4 v = make_float4(acc[i][j4 * 4 + 0], acc[i][j4 * 4 + 1],
                                       acc[i][j4 * 4 + 2], acc[i][j4 * 4 + 3]);
                *reinterpret_cast<float4*>(C + (size_t)row * BN + tx * TN + j4 * 4) = v;
            }
        }
    }
}

// ---------------------------------------------------------------------------
// Aggregation
// ---------------------------------------------------------------------------
__device__ __forceinline__ void red_add_v4(float* p, float x, float y, float z, float w) {
    asm volatile("red.global.add.v4.f32 [%0], {%1, %2, %3, %4};"
                 :: "l"(p), "f"(x), "f"(y), "f"(z), "f"(w)
                 : "memory");
}

// Init pass: out[i][:] = dinv[i]^2 * h[i][:]  (self-loop term; also initializes out)
template <int F>
__global__ void agg_init_kernel(const float* __restrict__ h, const float* __restrict__ dinv,
                                float* __restrict__ out, int n) {
    constexpr int F4 = F / 4;
    int idx = blockIdx.x * blockDim.x + threadIdx.x;
    if (idx >= n * F4) return;
    int i  = idx / F4;
    float s = __ldg(dinv + i);
    s = s * s;
    float4 v = __ldg(reinterpret_cast<const float4*>(h) + idx);
    v.x *= s; v.y *= s; v.z *= s; v.w *= s;
    reinterpret_cast<float4*>(out)[idx] = v;
}

// Edge pass, F=128: one warp per edge, one red.v4 per lane
__global__ void agg_edge_f128(const float* __restrict__ h, const int* __restrict__ ei,
                              const float* __restrict__ nrm, float* out, int e_cnt) {
    int gid  = blockIdx.x * blockDim.x + threadIdx.x;
    int e    = gid >> 5;
    int lane = gid & 31;
    if (e >= e_cnt) return;
    int   s = __ldg(ei + e);
    int   d = __ldg(ei + e_cnt + e);
    float w = __ldg(nrm + e);
    float4 v = __ldg(reinterpret_cast<const float4*>(h + (size_t)s * 128) + lane);
    red_add_v4(out + (size_t)d * 128 + lane * 4, v.x * w, v.y * w, v.z * w, v.w * w);
}

// Edge pass, F=64: half-warp per edge
__global__ void agg_edge_f64(const float* __restrict__ h, const int* __restrict__ ei,
                             const float* __restrict__ nrm, float* out, int e_cnt) {
    int gid  = blockIdx.x * blockDim.x + threadIdx.x;
    int e    = gid >> 4;
    int lane = gid & 15;
    if (e >= e_cnt) return;
    int   s = __ldg(ei + e);
    int   d = __ldg(ei + e_cnt + e);
    float w = __ldg(nrm + e);
    float4 v = __ldg(reinterpret_cast<const float4*>(h + (size_t)s * 64) + lane);
    red_add_v4(out + (size_t)d * 64 + lane * 4, v.x * w, v.y * w, v.z * w, v.w * w);
}

// Bias (+ optional ReLU) epilogue
template <int F, bool RELU>
__global__ void bias_kernel(float* __restrict__ out, const float* __restrict__ bias, int n) {
    constexpr int F4 = F / 4;
    int idx = blockIdx.x * blockDim.x + threadIdx.x;
    if (idx >= n * F4) return;
    int c = idx & (F4 - 1);
    float4 b4 = __ldg(reinterpret_cast<const float4*>(bias) + c);
    float4 v  = reinterpret_cast<float4*>(out)[idx];
    v.x += b4.x; v.y += b4.y; v.z += b4.z; v.w += b4.w;
    if (RELU) {
        v.x = fmaxf(v.x, 0.f); v.y = fmaxf(v.y, 0.f);
        v.z = fmaxf(v.z, 0.f); v.w = fmaxf(v.w, 0.f);
    }
    reinterpret_cast<float4*>(out)[idx] = v;
}

// ---------------------------------------------------------------------------
// Launcher
// ---------------------------------------------------------------------------
extern "C" void kernel_launch(void* const* d_in, const int* in_sizes, int n_in,
                              void* d_out, int out_size) {
    const float* x   = (const float*)d_in[0];
    const int*   ei  = (const int*)d_in[1];     // int32 edge_index [2, E]
    const float* W1  = (const float*)d_in[2];
    const float* b1  = (const float*)d_in[3];
    const float* W2  = (const float*)d_in[4];
    const float* b2  = (const float*)d_in[5];
    const float* W3  = (const float*)d_in[6];
    const float* b3  = (const float*)d_in[7];
    float*       out = (float*)d_out;

    const int E = in_sizes[1] / 2;      // 1,600,000
    const int N = in_sizes[0] / FEAT;   // 100,000

    void *pA, *pB, *pC, *pDinv, *pNorm, *pDeg;
    cudaGetSymbolAddress(&pA, g_bufA);
    cudaGetSymbolAddress(&pB, g_bufB);
    cudaGetSymbolAddress(&pC, g_bufC);
    cudaGetSymbolAddress(&pDinv, g_dinv);
    cudaGetSymbolAddress(&pNorm, g_norm);
    cudaGetSymbolAddress(&pDeg, g_deg);
    float* bufA = (float*)pA;
    float* bufB = (float*)pB;
    float* bufC = (float*)pC;
    float* dinv = (float*)pDinv;
    float* nrm  = (float*)pNorm;
    int*   deg  = (int*)pDeg;

    const int T = 256;
    const int gN   = (N + T - 1) / T;
    const int gE   = (E + T - 1) / T;
    const int gM   = (N + 127) / 128;                       // GEMM row blocks
    const int g128 = ((size_t)N * (HID / 4) + T - 1) / T;   // N*32 threads
    const int g64  = ((size_t)N * (OUTF / 4) + T - 1) / T;  // N*16 threads
    const int gE32 = ((size_t)E * 32 + T - 1) / T;          // warp per edge
    const int gE16 = ((size_t)E * 16 + T - 1) / T;          // half-warp per edge

    // ---- prep: degree, dinv, per-edge norm ----
    k_deg_init<<<gN, T>>>(deg, N);
    k_deg_count<<<gE, T>>>(ei, deg, E);
    k_dinv<<<gN, T>>>(deg, dinv, N);
    k_norm<<<gE, T>>>(ei, dinv, nrm, E);

    // ---- layer 1: x@W1 -> A ; agg(A) -> B ; relu(B+b1) ----
    gemm_kernel<16, 128, 8, 8><<<gM, 256>>>(x, W1, bufA, N, FEAT);
    agg_init_kernel<128><<<g128, T>>>(bufA, dinv, bufB, N);
    agg_edge_f128<<<gE32, T>>>(bufA, ei, nrm, bufB, E);
    bias_kernel<128, true><<<g128, T>>>(bufB, b1, N);

    // ---- layer 2: B@W2 -> A ; agg(A) -> B ; relu(B+b2) ----
    gemm_kernel<16, 128, 8, 8><<<gM, 256>>>(bufB, W2, bufA, N, HID);
    agg_init_kernel<128><<<g128, T>>>(bufA, dinv, bufB, N);
    agg_edge_f128<<<gE32, T>>>(bufA, ei, nrm, bufB, E);
    bias_kernel<128, true><<<g128, T>>>(bufB, b2, N);

    // ---- layer 3: B@W3 -> C ; agg(C) -> out ; out+b3 ----
    gemm_kernel<16, 64, 8, 4><<<gM, 256>>>(bufB, W3, bufC, N, HID);
    agg_init_kernel<64><<<g64, T>>>(bufC, dinv, out, N);
    agg_edge_f64<<<gE16, T>>>(bufC, ei, nrm, out, E);
    bias_kernel<64, false><<<g64, T>>>(out, b3, N);
}

// round 3
// speedup vs baseline: 1.7650x; 1.7650x over previous
#include <cuda_runtime.h>
#include <cuda_bf16.h>
#include <cstdint>
#include <cstddef>

// Problem constants (fixed by the dataset)
#define NN   100000
#define FEAT 256
#define HID  128
#define OUTF 64
#define EE   1600000
#define SCAN_NB ((NN + 255) / 256)   // 391

// ---------------------------------------------------------------------------
// Static device scratch (allocation-free rule: __device__ globals)
// ---------------------------------------------------------------------------
__device__ __align__(16) float g_bufA[(size_t)NN * HID];   // 51.2 MB
__device__ __align__(16) float g_bufB[(size_t)NN * HID];   // 51.2 MB
__device__ __align__(16) float g_bufC[(size_t)NN * OUTF];  // 25.6 MB
__device__ __align__(16) float g_dinv[NN];
__device__ __align__(16) int   g_deg[NN];
__device__ __align__(16) int   g_rowptr[NN];
__device__ __align__(16) int   g_cursor[NN];
__device__ __align__(16) int   g_blocksum[512];
__device__ __align__(16) int2  g_csr[EE];                  // {src, norm-as-int}

// ---------------------------------------------------------------------------
// Prep: degree, dinv, CSR build (histogram -> scan -> scatter)
// edge_index is int32 (JAX x64 disabled -> int64 request silently becomes int32)
// ---------------------------------------------------------------------------
__global__ void k_deg_init(int* deg, int n) {
    int i = blockIdx.x * blockDim.x + threadIdx.x;
    if (i < n) deg[i] = 1;  // self-loop
}

__global__ void k_deg_count(const int* __restrict__ ei, int* deg, int e_cnt) {
    int e = blockIdx.x * blockDim.x + threadIdx.x;
    if (e < e_cnt) atomicAdd(deg + ei[e_cnt + e], 1);
}

__global__ void k_dinv(const int* __restrict__ deg, float* dinv, int n) {
    int i = blockIdx.x * blockDim.x + threadIdx.x;
    if (i < n) dinv[i] = rsqrtf((float)deg[i]);
}

// Exclusive scan of (deg[i]-1) over N elements, 3-phase
__global__ void k_scan_block(const int* __restrict__ deg, int* rowptr, int* blocksum, int n) {
    __shared__ int s[256];
    int i = blockIdx.x * 256 + threadIdx.x;
    int v = (i < n) ? deg[i] - 1 : 0;
    s[threadIdx.x] = v;
    __syncthreads();
#pragma unroll
    for (int off = 1; off < 256; off <<= 1) {
        int t = (threadIdx.x >= off) ? s[threadIdx.x - off] : 0;
        __syncthreads();
        s[threadIdx.x] += t;
        __syncthreads();
    }
    if (i < n) rowptr[i] = s[threadIdx.x] - v;  // exclusive
    if (threadIdx.x == 255) blocksum[blockIdx.x] = s[255];
}

__global__ void k_scan_mid(int* blocksum, int nb) {
    __shared__ int s[512];
    int i = threadIdx.x;
    int v = (i < nb) ? blocksum[i] : 0;
    s[i] = v;
    __syncthreads();
#pragma unroll
    for (int off = 1; off < 512; off <<= 1) {
        int t = (i >= off) ? s[i - off] : 0;
        __syncthreads();
        s[i] += t;
        __syncthreads();
    }
    if (i < nb) blocksum[i] = s[i] - v;  // exclusive
}

__global__ void k_scan_add(int* rowptr, int* cursor, const int* __restrict__ blocksum, int n) {
    int i = blockIdx.x * blockDim.x + threadIdx.x;
    if (i < n) {
        int r = rowptr[i] + blocksum[i >> 8];
        rowptr[i] = r;
        cursor[i] = r;
    }
}

__global__ void k_scatter(const int* __restrict__ ei, const float* __restrict__ dinv,
                          int* cursor, int2* __restrict__ csr, int e_cnt) {
    int e = blockIdx.x * blockDim.x + threadIdx.x;
    if (e >= e_cnt) return;
    int s = ei[e];
    int d = ei[e_cnt + e];
    float w = __ldg(dinv + s) * __ldg(dinv + d);
    int pos = atomicAdd(cursor + d, 1);
    csr[pos] = make_int2(s, __float_as_int(w));
}

// ---------------------------------------------------------------------------
// SGEMM: C[M,BN] = relu?(A)[M,K] @ W[K,BN], fp32, 128-row tiles
// ---------------------------------------------------------------------------
template <int BK, int BN, int TM, int TN, bool RELU>
__global__ void __launch_bounds__(256, 2)
gemm_kernel(const float* __restrict__ A, const float* __restrict__ W,
            float* __restrict__ C, int M, int K) {
    constexpr int BM  = 128;
    constexpr int NTH = (BM / TM) * (BN / TN);  // 256 for both configs
    __shared__ float As[BK][BM + 4];
    __shared__ float Ws[BK][BN];

    const int tid = threadIdx.x;
    const int m0  = blockIdx.x * BM;
    const int tx  = tid % (BN / TN);
    const int ty  = tid / (BN / TN);

    float acc[TM][TN];
#pragma unroll
    for (int i = 0; i < TM; i++)
#pragma unroll
        for (int j = 0; j < TN; j++) acc[i][j] = 0.0f;

    for (int k0 = 0; k0 < K; k0 += BK) {
        // Load A tile (BM x BK), optional ReLU, store transposed As[k][row]
#pragma unroll
        for (int i = tid; i < BM * (BK / 4); i += NTH) {
            int r  = i / (BK / 4);
            int c4 = i % (BK / 4);
            float4 v = make_float4(0.f, 0.f, 0.f, 0.f);
            if (m0 + r < M)
                v = *reinterpret_cast<const float4*>(A + (size_t)(m0 + r) * K + k0 + c4 * 4);
            if (RELU) {
                v.x = fmaxf(v.x, 0.f); v.y = fmaxf(v.y, 0.f);
                v.z = fmaxf(v.z, 0.f); v.w = fmaxf(v.w, 0.f);
            }
            As[c4 * 4 + 0][r] = v.x;
            As[c4 * 4 + 1][r] = v.y;
            As[c4 * 4 + 2][r] = v.z;
            As[c4 * 4 + 3][r] = v.w;
        }
        // Load W tile (BK x BN)
#pragma unroll
        for (int i = tid; i < BK * (BN / 4); i += NTH) {
            int r  = i / (BN / 4);
            int c4 = i % (BN / 4);
            *reinterpret_cast<float4*>(&Ws[r][c4 * 4]) =
                *reinterpret_cast<const float4*>(W + (size_t)(k0 + r) * BN + c4 * 4);
        }
        __syncthreads();

#pragma unroll
        for (int k = 0; k < BK; k++) {
            float a[TM], b[TN];
#pragma unroll
            for (int i = 0; i < TM; i++) a[i] = As[k][ty * TM + i];
#pragma unroll
            for (int j = 0; j < TN; j++) b[j] = Ws[k][tx * TN + j];
#pragma unroll
            for (int i = 0; i < TM; i++)
#pragma unroll
                for (int j = 0; j < TN; j++) acc[i][j] = fmaf(a[i], b[j], acc[i][j]);
        }
        __syncthreads();
    }

#pragma unroll
    for (int i = 0; i < TM; i++) {
        int row = m0 + ty * TM + i;
        if (row < M) {
#pragma unroll
            for (int j4 = 0; j4 < TN / 4; j4++) {
                float4 v = make_float4(acc[i][j4 * 4 + 0], acc[i][j4 * 4 + 1],
                                       acc[i][j4 * 4 + 2], acc[i][j4 * 4 + 3]);
                *reinterpret_cast<float4*>(C + (size_t)row * BN + tx * TN + j4 * 4) = v;
            }
        }
    }
}

// ---------------------------------------------------------------------------
// CSR aggregation: warp per destination node.
// out[d] = dinv[d]^2 * h[d] + sum_{e in in(d)} w_e * h[src_e] + bias
// F=128: lane owns float4; F=64: lane owns float2.
// ---------------------------------------------------------------------------
__global__ void agg_csr_f128(const float* __restrict__ h, const int2* __restrict__ csr,
                             const int* __restrict__ rowptr, const float* __restrict__ dinv,
                             const float* __restrict__ bias, float* __restrict__ out,
                             int n, int e_cnt) {
    int warp = (blockIdx.x * blockDim.x + threadIdx.x) >> 5;
    int lane = threadIdx.x & 31;
    if (warp >= n) return;
    const int d = warp;

    float di = __ldg(dinv + d);
    di *= di;
    float4 acc = __ldg(reinterpret_cast<const float4*>(h + (size_t)d * 128) + lane);
    float4 b4  = __ldg(reinterpret_cast<const float4*>(bias) + lane);
    acc.x = acc.x * di + b4.x;
    acc.y = acc.y * di + b4.y;
    acc.z = acc.z * di + b4.z;
    acc.w = acc.w * di + b4.w;

    int start = __ldg(rowptr + d);
    int end   = (d == n - 1) ? e_cnt : __ldg(rowptr + d + 1);

    for (int base = start; base < end; base += 32) {
        int m = min(32, end - base);
        int2 ew = make_int2(0, 0);
        if (lane < m) ew = __ldg(csr + base + lane);
        for (int j = 0; j < m; j++) {
            int   s = __shfl_sync(0xffffffffu, ew.x, j);
            float w = __int_as_float(__shfl_sync(0xffffffffu, ew.y, j));
            float4 v = __ldg(reinterpret_cast<const float4*>(h + (size_t)s * 128) + lane);
            acc.x = fmaf(w, v.x, acc.x);
            acc.y = fmaf(w, v.y, acc.y);
            acc.z = fmaf(w, v.z, acc.z);
            acc.w = fmaf(w, v.w, acc.w);
        }
    }
    *(reinterpret_cast<float4*>(out + (size_t)d * 128) + lane) = acc;
}

__global__ void agg_csr_f64(const float* __restrict__ h, const int2* __restrict__ csr,
                            const int* __restrict__ rowptr, const float* __restrict__ dinv,
                            const float* __restrict__ bias, float* __restrict__ out,
                            int n, int e_cnt) {
    int warp = (blockIdx.x * blockDim.x + threadIdx.x) >> 5;
    int lane = threadIdx.x & 31;
    if (warp >= n) return;
    const int d = warp;

    float di = __ldg(dinv + d);
    di *= di;
    float2 acc = __ldg(reinterpret_cast<const float2*>(h + (size_t)d * 64) + lane);
    float2 b2  = __ldg(reinterpret_cast<const float2*>(bias) + lane);
    acc.x = acc.x * di + b2.x;
    acc.y = acc.y * di + b2.y;

    int start = __ldg(rowptr + d);
    int end   = (d == n - 1) ? e_cnt : __ldg(rowptr + d + 1);

    for (int base = start; base < end; base += 32) {
        int m = min(32, end - base);
        int2 ew = make_int2(0, 0);
        if (lane < m) ew = __ldg(csr + base + lane);
        for (int j = 0; j < m; j++) {
            int   s = __shfl_sync(0xffffffffu, ew.x, j);
            float w = __int_as_float(__shfl_sync(0xffffffffu, ew.y, j));
            float2 v = __ldg(reinterpret_cast<const float2*>(h + (size_t)s * 64) + lane);
            acc.x = fmaf(w, v.x, acc.x);
            acc.y = fmaf(w, v.y, acc.y);
        }
    }
    *(reinterpret_cast<float2*>(out + (size_t)d * 64) + lane) = acc;
}

// ---------------------------------------------------------------------------
// Launcher
// ---------------------------------------------------------------------------
extern "C" void kernel_launch(void* const* d_in, const int* in_sizes, int n_in,
                              void* d_out, int out_size) {
    const float* x   = (const float*)d_in[0];
    const int*   ei  = (const int*)d_in[1];     // int32 edge_index [2, E]
    const float* W1  = (const float*)d_in[2];
    const float* b1  = (const float*)d_in[3];
    const float* W2  = (const float*)d_in[4];
    const float* b2  = (const float*)d_in[5];
    const float* W3  = (const float*)d_in[6];
    const float* b3  = (const float*)d_in[7];
    float*       out = (float*)d_out;

    const int E = in_sizes[1] / 2;      // 1,600,000
    const int N = in_sizes[0] / FEAT;   // 100,000

    void *pA, *pB, *pC, *pDinv, *pDeg, *pRow, *pCur, *pBS, *pCsr;
    cudaGetSymbolAddress(&pA, g_bufA);
    cudaGetSymbolAddress(&pB, g_bufB);
    cudaGetSymbolAddress(&pC, g_bufC);
    cudaGetSymbolAddress(&pDinv, g_dinv);
    cudaGetSymbolAddress(&pDeg, g_deg);
    cudaGetSymbolAddress(&pRow, g_rowptr);
    cudaGetSymbolAddress(&pCur, g_cursor);
    cudaGetSymbolAddress(&pBS, g_blocksum);
    cudaGetSymbolAddress(&pCsr, g_csr);
    float* bufA   = (float*)pA;
    float* bufB   = (float*)pB;
    float* bufC   = (float*)pC;
    float* dinv   = (float*)pDinv;
    int*   deg    = (int*)pDeg;
    int*   rowptr = (int*)pRow;
    int*   cursor = (int*)pCur;
    int*   bsum   = (int*)pBS;
    int2*  csr    = (int2*)pCsr;

    const int T  = 256;
    const int gN = (N + T - 1) / T;
    const int gE = (E + T - 1) / T;
    const int gM = (N + 127) / 128;                     // GEMM row blocks
    const int gW = ((size_t)N * 32 + T - 1) / T;        // warp per node

    // ---- prep: degree, dinv, CSR ----
    k_deg_init<<<gN, T>>>(deg, N);
    k_deg_count<<<gE, T>>>(ei, deg, E);
    k_dinv<<<gN, T>>>(deg, dinv, N);
    k_scan_block<<<SCAN_NB, 256>>>(deg, rowptr, bsum, N);
    k_scan_mid<<<1, 512>>>(bsum, SCAN_NB);
    k_scan_add<<<gN, T>>>(rowptr, cursor, bsum, N);
    k_scatter<<<gE, T>>>(ei, dinv, cursor, csr, E);

    // ---- layer 1: x@W1 -> A ; csr-agg(A)+b1 -> B ----
    gemm_kernel<16, 128, 8, 8, false><<<gM, 256>>>(x, W1, bufA, N, FEAT);
    agg_csr_f128<<<gW, T>>>(bufA, csr, rowptr, dinv, b1, bufB, N, E);

    // ---- layer 2: relu(B)@W2 -> A ; csr-agg(A)+b2 -> B ----
    gemm_kernel<16, 128, 8, 8, true><<<gM, 256>>>(bufB, W2, bufA, N, HID);
    agg_csr_f128<<<gW, T>>>(bufA, csr, rowptr, dinv, b2, bufB, N, E);

    // ---- layer 3: relu(B)@W3 -> C ; csr-agg(C)+b3 -> out ----
    gemm_kernel<16, 64, 8, 4, true><<<gM, 256>>>(bufB, W3, bufC, N, HID);
    agg_csr_f64<<<gW, T>>>(bufC, csr, rowptr, dinv, b3, out, N, E);
}

// round 4
// speedup vs baseline: 2.4330x; 1.3785x over previous
#include <cuda_runtime.h>
#include <cuda_bf16.h>
#include <cstdint>
#include <cstddef>

// Problem constants (fixed by the dataset)
#define NN   100000
#define FEAT 256
#define HID  128
#define OUTF 64
#define EE   1600000
#define SCAN_NB ((NN + 255) / 256)   // 391

// ---------------------------------------------------------------------------
// Static device scratch (allocation-free rule: __device__ globals)
// ---------------------------------------------------------------------------
__device__ __align__(16) float g_bufA[(size_t)NN * HID];   // 51.2 MB
__device__ __align__(16) float g_bufB[(size_t)NN * HID];   // 51.2 MB
__device__ __align__(16) float g_bufC[(size_t)NN * OUTF];  // 25.6 MB
__device__ __align__(16) float g_dinv[NN];
__device__ __align__(16) int   g_deg[NN];
__device__ __align__(16) int   g_rowptr[NN];
__device__ __align__(16) int   g_cursor[NN];
__device__ __align__(16) int   g_blocksum[512];
__device__ __align__(16) int2  g_csr[EE];                  // {src, norm-as-int}

// ---------------------------------------------------------------------------
// Prep: degree, dinv, CSR build (histogram -> scan -> scatter)
// edge_index is int32 (JAX x64 disabled -> int64 request silently becomes int32)
// ---------------------------------------------------------------------------
__global__ void k_deg_init(int* deg, int n) {
    int i = blockIdx.x * blockDim.x + threadIdx.x;
    if (i < n) deg[i] = 1;  // self-loop
}

__global__ void k_deg_count(const int* __restrict__ ei, int* deg, int e_cnt) {
    int e = blockIdx.x * blockDim.x + threadIdx.x;
    if (e < e_cnt) atomicAdd(deg + ei[e_cnt + e], 1);
}

__global__ void k_dinv(const int* __restrict__ deg, float* dinv, int n) {
    int i = blockIdx.x * blockDim.x + threadIdx.x;
    if (i < n) dinv[i] = rsqrtf((float)deg[i]);
}

__global__ void k_scan_block(const int* __restrict__ deg, int* rowptr, int* blocksum, int n) {
    __shared__ int s[256];
    int i = blockIdx.x * 256 + threadIdx.x;
    int v = (i < n) ? deg[i] - 1 : 0;
    s[threadIdx.x] = v;
    __syncthreads();
#pragma unroll
    for (int off = 1; off < 256; off <<= 1) {
        int t = (threadIdx.x >= off) ? s[threadIdx.x - off] : 0;
        __syncthreads();
        s[threadIdx.x] += t;
        __syncthreads();
    }
    if (i < n) rowptr[i] = s[threadIdx.x] - v;  // exclusive
    if (threadIdx.x == 255) blocksum[blockIdx.x] = s[255];
}

__global__ void k_scan_mid(int* blocksum, int nb) {
    __shared__ int s[512];
    int i = threadIdx.x;
    int v = (i < nb) ? blocksum[i] : 0;
    s[i] = v;
    __syncthreads();
#pragma unroll
    for (int off = 1; off < 512; off <<= 1) {
        int t = (i >= off) ? s[i - off] : 0;
        __syncthreads();
        s[i] += t;
        __syncthreads();
    }
    if (i < nb) blocksum[i] = s[i] - v;  // exclusive
}

__global__ void k_scan_add(int* rowptr, int* cursor, const int* __restrict__ blocksum, int n) {
    int i = blockIdx.x * blockDim.x + threadIdx.x;
    if (i < n) {
        int r = rowptr[i] + blocksum[i >> 8];
        rowptr[i] = r;
        cursor[i] = r;
    }
}

__global__ void k_scatter(const int* __restrict__ ei, const float* __restrict__ dinv,
                          int* cursor, int2* __restrict__ csr, int e_cnt) {
    int e = blockIdx.x * blockDim.x + threadIdx.x;
    if (e >= e_cnt) return;
    int s = ei[e];
    int d = ei[e_cnt + e];
    float w = __ldg(dinv + s) * __ldg(dinv + d);
    int pos = atomicAdd(cursor + d, 1);
    csr[pos] = make_int2(s, __float_as_int(w));
}

// ---------------------------------------------------------------------------
// Split-bf16 tensor-core GEMM (3xBF16 scheme, fp32-grade accuracy)
// C[M,BN] = relu?(A)[M,K] @ W[K,BN]
// mma.sync.m16n8k16.row.col: A row-major [m][k], B col-major (staged [n][k])
// ---------------------------------------------------------------------------
__device__ __forceinline__ uint32_t pack2bf(float x0, float x1) {
    uint32_t l = __bfloat16_as_ushort(__float2bfloat16_rn(x0));
    uint32_t h = __bfloat16_as_ushort(__float2bfloat16_rn(x1));
    return l | (h << 16);
}

__device__ __forceinline__ void split_bf(float x, float& hi, float& lo) {
    __nv_bfloat16 b = __float2bfloat16_rn(x);
    hi = __bfloat162float(b);
    lo = x - hi;
}

__device__ __forceinline__ void mma_bf16(float* c, const uint32_t* a, uint32_t b0, uint32_t b1) {
    asm volatile(
        "mma.sync.aligned.m16n8k16.row.col.f32.bf16.bf16.f32 "
        "{%0,%1,%2,%3}, {%4,%5,%6,%7}, {%8,%9}, {%0,%1,%2,%3};"
        : "+f"(c[0]), "+f"(c[1]), "+f"(c[2]), "+f"(c[3])
        : "r"(a[0]), "r"(a[1]), "r"(a[2]), "r"(a[3]), "r"(b0), "r"(b1));
}

template <int BN, bool RELU>
__global__ void __launch_bounds__(256, 2)
gemm_tc_kernel(const float* __restrict__ A, const float* __restrict__ W,
               float* __restrict__ C, int M, int K) {
    constexpr int BM = 128;
    constexpr int BK = 32;
    constexpr int AW = 20;            // words (b32) per staged row: 16 data + 4 pad
    constexpr int WN = BN / 2;        // warp n-tile (64 or 32)
    constexpr int NFRAG = WN / 8;     // 8 or 4

    __shared__ uint32_t as_hi[BM * AW], as_lo[BM * AW];
    __shared__ uint32_t bs_hi[BN * AW], bs_lo[BN * AW];

    const int tid  = threadIdx.x;
    const int lane = tid & 31;
    const int wid  = tid >> 5;
    const int wm   = wid & 3;         // 4 m-warps * 32 rows
    const int wn   = wid >> 2;        // 2 n-warps * WN cols
    const int g    = lane >> 2;
    const int q    = lane & 3;
    const int m0   = blockIdx.x * BM;

    float acc[2][NFRAG][4];
#pragma unroll
    for (int mi = 0; mi < 2; mi++)
#pragma unroll
        for (int j = 0; j < NFRAG; j++)
#pragma unroll
            for (int t = 0; t < 4; t++) acc[mi][j][t] = 0.0f;

    for (int k0 = 0; k0 < K; k0 += BK) {
        // ---- stage A tile (BM x BK): fp32 -> split bf16 hi/lo, row-major ----
#pragma unroll
        for (int it = 0; it < (BM * BK / 4) / 256; it++) {
            int i  = tid + it * 256;
            int m  = i >> 3;          // BK/4 = 8 float4 per row
            int k4 = i & 7;
            float4 v = make_float4(0.f, 0.f, 0.f, 0.f);
            if (m0 + m < M)
                v = __ldg(reinterpret_cast<const float4*>(A + (size_t)(m0 + m) * K + k0 + k4 * 4));
            if (RELU) {
                v.x = fmaxf(v.x, 0.f); v.y = fmaxf(v.y, 0.f);
                v.z = fmaxf(v.z, 0.f); v.w = fmaxf(v.w, 0.f);
            }
            float hx, lx, hy, ly, hz, lz, hw, lw;
            split_bf(v.x, hx, lx); split_bf(v.y, hy, ly);
            split_bf(v.z, hz, lz); split_bf(v.w, hw, lw);
            int base = m * AW + k4 * 2;
            as_hi[base]     = pack2bf(hx, hy);
            as_hi[base + 1] = pack2bf(hz, hw);
            as_lo[base]     = pack2bf(lx, ly);
            as_lo[base + 1] = pack2bf(lz, lw);
        }
        // ---- stage B tile (BK x BN) transposed to [n][k] with XOR swizzle ----
#pragma unroll
        for (int it = 0; it < (BK / 2 * BN) / 256; it++) {
            int i  = tid + it * 256;
            int n  = i % BN;          // adjacent threads -> adjacent n (coalesced reads)
            int kw = i / BN;          // 0..15
            float x0 = __ldg(W + (size_t)(k0 + 2 * kw) * BN + n);
            float x1 = __ldg(W + (size_t)(k0 + 2 * kw + 1) * BN + n);
            float h0, l0, h1, l1;
            split_bf(x0, h0, l0); split_bf(x1, h1, l1);
            int sw = kw ^ ((n >> 3) & 7);
            bs_hi[n * AW + sw] = pack2bf(h0, h1);
            bs_lo[n * AW + sw] = pack2bf(l0, l1);
        }
        __syncthreads();

        // ---- 2 k16 steps per BK ----
#pragma unroll
        for (int kk = 0; kk < BK; kk += 16) {
            const int kwb = (kk >> 1) + q;  // word base for this lane
            // A fragments (2 m-frags, hi+lo)
            uint32_t a_hi[2][4], a_lo[2][4];
#pragma unroll
            for (int mi = 0; mi < 2; mi++) {
                int r0 = (wm * 32 + mi * 16 + g) * AW;
                int r8 = r0 + 8 * AW;
                a_hi[mi][0] = as_hi[r0 + kwb];
                a_hi[mi][1] = as_hi[r8 + kwb];
                a_hi[mi][2] = as_hi[r0 + kwb + 4];
                a_hi[mi][3] = as_hi[r8 + kwb + 4];
                a_lo[mi][0] = as_lo[r0 + kwb];
                a_lo[mi][1] = as_lo[r8 + kwb];
                a_lo[mi][2] = as_lo[r0 + kwb + 4];
                a_lo[mi][3] = as_lo[r8 + kwb + 4];
            }
#pragma unroll
            for (int j = 0; j < NFRAG; j++) {
                int n  = wn * WN + 8 * j + g;
                int v  = (n >> 3) & 7;
                int nb = n * AW;
                uint32_t bh0 = bs_hi[nb + (kwb ^ v)];
                uint32_t bh1 = bs_hi[nb + ((kwb + 4) ^ v)];
                uint32_t bl0 = bs_lo[nb + (kwb ^ v)];
                uint32_t bl1 = bs_lo[nb + ((kwb + 4) ^ v)];
#pragma unroll
                for (int mi = 0; mi < 2; mi++) {
                    mma_bf16(acc[mi][j], a_hi[mi], bh0, bh1);
                    mma_bf16(acc[mi][j], a_hi[mi], bl0, bl1);
                    mma_bf16(acc[mi][j], a_lo[mi], bh0, bh1);
                }
            }
        }
        __syncthreads();
    }

    // ---- epilogue: write C fragments ----
#pragma unroll
    for (int mi = 0; mi < 2; mi++) {
        int row = m0 + wm * 32 + mi * 16 + g;
#pragma unroll
        for (int j = 0; j < NFRAG; j++) {
            int col = wn * WN + 8 * j + q * 2;
            if (row < M)
                *reinterpret_cast<float2*>(C + (size_t)row * BN + col) =
                    make_float2(acc[mi][j][0], acc[mi][j][1]);
            if (row + 8 < M)
                *reinterpret_cast<float2*>(C + (size_t)(row + 8) * BN + col) =
                    make_float2(acc[mi][j][2], acc[mi][j][3]);
        }
    }
}

// ---------------------------------------------------------------------------
// CSR aggregation: warp per destination node.
// out[d] = dinv[d]^2 * h[d] + sum_{e in in(d)} w_e * h[src_e] + bias
// ---------------------------------------------------------------------------
__global__ void agg_csr_f128(const float* __restrict__ h, const int2* __restrict__ csr,
                             const int* __restrict__ rowptr, const float* __restrict__ dinv,
                             const float* __restrict__ bias, float* __restrict__ out,
                             int n, int e_cnt) {
    int warp = (blockIdx.x * blockDim.x + threadIdx.x) >> 5;
    int lane = threadIdx.x & 31;
    if (warp >= n) return;
    const int d = warp;

    float di = __ldg(dinv + d);
    di *= di;
    float4 acc = __ldg(reinterpret_cast<const float4*>(h + (size_t)d * 128) + lane);
    float4 b4  = __ldg(reinterpret_cast<const float4*>(bias) + lane);
    acc.x = acc.x * di + b4.x;
    acc.y = acc.y * di + b4.y;
    acc.z = acc.z * di + b4.z;
    acc.w = acc.w * di + b4.w;

    int start = __ldg(rowptr + d);
    int end   = (d == n - 1) ? e_cnt : __ldg(rowptr + d + 1);

    for (int base = start; base < end; base += 32) {
        int m = min(32, end - base);
        int2 ew = make_int2(0, 0);
        if (lane < m) ew = __ldg(csr + base + lane);
        for (int j = 0; j < m; j++) {
            int   s = __shfl_sync(0xffffffffu, ew.x, j);
            float w = __int_as_float(__shfl_sync(0xffffffffu, ew.y, j));
            float4 v = __ldg(reinterpret_cast<const float4*>(h + (size_t)s * 128) + lane);
            acc.x = fmaf(w, v.x, acc.x);
            acc.y = fmaf(w, v.y, acc.y);
            acc.z = fmaf(w, v.z, acc.z);
            acc.w = fmaf(w, v.w, acc.w);
        }
    }
    *(reinterpret_cast<float4*>(out + (size_t)d * 128) + lane) = acc;
}

__global__ void agg_csr_f64(const float* __restrict__ h, const int2* __restrict__ csr,
                            const int* __restrict__ rowptr, const float* __restrict__ dinv,
                            const float* __restrict__ bias, float* __restrict__ out,
                            int n, int e_cnt) {
    int warp = (blockIdx.x * blockDim.x + threadIdx.x) >> 5;
    int lane = threadIdx.x & 31;
    if (warp >= n) return;
    const int d = warp;

    float di = __ldg(dinv + d);
    di *= di;
    float2 acc = __ldg(reinterpret_cast<const float2*>(h + (size_t)d * 64) + lane);
    float2 b2  = __ldg(reinterpret_cast<const float2*>(bias) + lane);
    acc.x = acc.x * di + b2.x;
    acc.y = acc.y * di + b2.y;

    int start = __ldg(rowptr + d);
    int end   = (d == n - 1) ? e_cnt : __ldg(rowptr + d + 1);

    for (int base = start; base < end; base += 32) {
        int m = min(32, end - base);
        int2 ew = make_int2(0, 0);
        if (lane < m) ew = __ldg(csr + base + lane);
        for (int j = 0; j < m; j++) {
            int   s = __shfl_sync(0xffffffffu, ew.x, j);
            float w = __int_as_float(__shfl_sync(0xffffffffu, ew.y, j));
            float2 v = __ldg(reinterpret_cast<const float2*>(h + (size_t)s * 64) + lane);
            acc.x = fmaf(w, v.x, acc.x);
            acc.y = fmaf(w, v.y, acc.y);
        }
    }
    *(reinterpret_cast<float2*>(out + (size_t)d * 64) + lane) = acc;
}

// ---------------------------------------------------------------------------
// Launcher
// ---------------------------------------------------------------------------
extern "C" void kernel_launch(void* const* d_in, const int* in_sizes, int n_in,
                              void* d_out, int out_size) {
    const float* x   = (const float*)d_in[0];
    const int*   ei  = (const int*)d_in[1];     // int32 edge_index [2, E]
    const float* W1  = (const float*)d_in[2];
    const float* b1  = (const float*)d_in[3];
    const float* W2  = (const float*)d_in[4];
    const float* b2  = (const float*)d_in[5];
    const float* W3  = (const float*)d_in[6];
    const float* b3  = (const float*)d_in[7];
    float*       out = (float*)d_out;

    const int E = in_sizes[1] / 2;      // 1,600,000
    const int N = in_sizes[0] / FEAT;   // 100,000

    void *pA, *pB, *pC, *pDinv, *pDeg, *pRow, *pCur, *pBS, *pCsr;
    cudaGetSymbolAddress(&pA, g_bufA);
    cudaGetSymbolAddress(&pB, g_bufB);
    cudaGetSymbolAddress(&pC, g_bufC);
    cudaGetSymbolAddress(&pDinv, g_dinv);
    cudaGetSymbolAddress(&pDeg, g_deg);
    cudaGetSymbolAddress(&pRow, g_rowptr);
    cudaGetSymbolAddress(&pCur, g_cursor);
    cudaGetSymbolAddress(&pBS, g_blocksum);
    cudaGetSymbolAddress(&pCsr, g_csr);
    float* bufA   = (float*)pA;
    float* bufB   = (float*)pB;
    float* bufC   = (float*)pC;
    float* dinv   = (float*)pDinv;
    int*   deg    = (int*)pDeg;
    int*   rowptr = (int*)pRow;
    int*   cursor = (int*)pCur;
    int*   bsum   = (int*)pBS;
    int2*  csr    = (int2*)pCsr;

    const int T  = 256;
    const int gN = (N + T - 1) / T;
    const int gE = (E + T - 1) / T;
    const int gM = (N + 127) / 128;                     // GEMM row blocks
    const int gW = ((size_t)N * 32 + T - 1) / T;        // warp per node

    // ---- prep: degree, dinv, CSR ----
    k_deg_init<<<gN, T>>>(deg, N);
    k_deg_count<<<gE, T>>>(ei, deg, E);
    k_dinv<<<gN, T>>>(deg, dinv, N);
    k_scan_block<<<SCAN_NB, 256>>>(deg, rowptr, bsum, N);
    k_scan_mid<<<1, 512>>>(bsum, SCAN_NB);
    k_scan_add<<<gN, T>>>(rowptr, cursor, bsum, N);
    k_scatter<<<gE, T>>>(ei, dinv, cursor, csr, E);

    // ---- layer 1: x@W1 -> A ; csr-agg(A)+b1 -> B ----
    gemm_tc_kernel<128, false><<<gM, 256>>>(x, W1, bufA, N, FEAT);
    agg_csr_f128<<<gW, T>>>(bufA, csr, rowptr, dinv, b1, bufB, N, E);

    // ---- layer 2: relu(B)@W2 -> A ; csr-agg(A)+b2 -> B ----
    gemm_tc_kernel<128, true><<<gM, 256>>>(bufB, W2, bufA, N, HID);
    agg_csr_f128<<<gW, T>>>(bufA, csr, rowptr, dinv, b2, bufB, N, E);

    // ---- layer 3: relu(B)@W3 -> C ; csr-agg(C)+b3 -> out ----
    gemm_tc_kernel<64, true><<<gM, 256>>>(bufB, W3, bufC, N, HID);
    agg_csr_f64<<<gW, T>>>(bufC, csr, rowptr, dinv, b3, out, N, E);
}

// round 5
// speedup vs baseline: 3.3769x; 1.3880x over previous
#include <cuda_runtime.h>
#include <cuda_bf16.h>
#include <cuda_fp16.h>
#include <cstdint>
#include <cstddef>

// Problem constants (fixed by the dataset)
#define NN   100000
#define FEAT 256
#define HID  128
#define OUTF 64
#define EE   1600000
#define SCAN_NB ((NN + 255) / 256)   // 391

// ---------------------------------------------------------------------------
// Static device scratch (allocation-free rule: __device__ globals)
// ---------------------------------------------------------------------------
__device__ __align__(16) __half g_hA[(size_t)NN * HID];   // 25.6 MB (GEMM out)
__device__ __align__(16) __half g_hB[(size_t)NN * HID];   // 25.6 MB (agg out)
__device__ __align__(16) __half g_hC[(size_t)NN * OUTF];  // 12.8 MB
__device__ __align__(16) float  g_dinv[NN];
__device__ __align__(16) int    g_deg[NN];
__device__ __align__(16) int    g_rowptr[NN];
__device__ __align__(16) int    g_cursor[NN];
__device__ __align__(16) int    g_blocksum[512];
__device__ __align__(16) int2   g_csr[EE];                // {src, norm-as-int}

// ---------------------------------------------------------------------------
// Prep: degree, dinv, CSR build (histogram -> scan -> scatter)
// edge_index is int32 (JAX x64 disabled -> int64 request silently becomes int32)
// ---------------------------------------------------------------------------
__global__ void k_deg_init(int* deg, int n) {
    int i = blockIdx.x * blockDim.x + threadIdx.x;
    if (i < n) deg[i] = 1;  // self-loop
}

__global__ void k_deg_count(const int* __restrict__ ei, int* deg, int e_cnt) {
    int e = blockIdx.x * blockDim.x + threadIdx.x;
    if (e < e_cnt) atomicAdd(deg + ei[e_cnt + e], 1);
}

__global__ void k_dinv(const int* __restrict__ deg, float* dinv, int n) {
    int i = blockIdx.x * blockDim.x + threadIdx.x;
    if (i < n) dinv[i] = rsqrtf((float)deg[i]);
}

__global__ void k_scan_block(const int* __restrict__ deg, int* rowptr, int* blocksum, int n) {
    __shared__ int s[256];
    int i = blockIdx.x * 256 + threadIdx.x;
    int v = (i < n) ? deg[i] - 1 : 0;
    s[threadIdx.x] = v;
    __syncthreads();
#pragma unroll
    for (int off = 1; off < 256; off <<= 1) {
        int t = (threadIdx.x >= off) ? s[threadIdx.x - off] : 0;
        __syncthreads();
        s[threadIdx.x] += t;
        __syncthreads();
    }
    if (i < n) rowptr[i] = s[threadIdx.x] - v;  // exclusive
    if (threadIdx.x == 255) blocksum[blockIdx.x] = s[255];
}

__global__ void k_scan_mid(int* blocksum, int nb) {
    __shared__ int s[512];
    int i = threadIdx.x;
    int v = (i < nb) ? blocksum[i] : 0;
    s[i] = v;
    __syncthreads();
#pragma unroll
    for (int off = 1; off < 512; off <<= 1) {
        int t = (i >= off) ? s[i - off] : 0;
        __syncthreads();
        s[i] += t;
        __syncthreads();
    }
    if (i < nb) blocksum[i] = s[i] - v;  // exclusive
}

__global__ void k_scan_add(int* rowptr, int* cursor, const int* __restrict__ blocksum, int n) {
    int i = blockIdx.x * blockDim.x + threadIdx.x;
    if (i < n) {
        int r = rowptr[i] + blocksum[i >> 8];
        rowptr[i] = r;
        cursor[i] = r;
    }
}

__global__ void k_scatter(const int* __restrict__ ei, const float* __restrict__ dinv,
                          int* cursor, int2* __restrict__ csr, int e_cnt) {
    int e = blockIdx.x * blockDim.x + threadIdx.x;
    if (e >= e_cnt) return;
    int s = ei[e];
    int d = ei[e_cnt + e];
    float w = __ldg(dinv + s) * __ldg(dinv + d);
    int pos = atomicAdd(cursor + d, 1);
    csr[pos] = make_int2(s, __float_as_int(w));
}

// ---------------------------------------------------------------------------
// fp16 tensor-core GEMM: C[M,BN](fp16) = A[M,K] @ W[K,BN](fp32->fp16)
// mma.sync.m16n8k16.row.col.f32.f16.f16.f32
// A_FP32: layer 1 reads fp32 x; otherwise A is fp16 (already post-ReLU).
// ---------------------------------------------------------------------------
__device__ __forceinline__ void mma_f16(float* c, const uint32_t* a, uint32_t b0, uint32_t b1) {
    asm volatile(
        "mma.sync.aligned.m16n8k16.row.col.f32.f16.f16.f32 "
        "{%0,%1,%2,%3}, {%4,%5,%6,%7}, {%8,%9}, {%0,%1,%2,%3};"
        : "+f"(c[0]), "+f"(c[1]), "+f"(c[2]), "+f"(c[3])
        : "r"(a[0]), "r"(a[1]), "r"(a[2]), "r"(a[3]), "r"(b0), "r"(b1));
}

__device__ __forceinline__ uint32_t pack_h2(float x0, float x1) {
    __half2 h = __floats2half2_rn(x0, x1);
    return *reinterpret_cast<uint32_t*>(&h);
}

template <int BN, bool A_FP32>
__global__ void __launch_bounds__(256, 2)
gemm_f16_kernel(const void* __restrict__ Ain, const float* __restrict__ W,
                __half* __restrict__ C, int M, int K) {
    constexpr int BM = 128;
    constexpr int BK = 32;
    constexpr int AW = 20;            // b32 words per staged row: 16 data + 4 pad
    constexpr int WN = BN / 2;        // warp n-tile (64 or 32)
    constexpr int NFRAG = WN / 8;     // 8 or 4

    __shared__ uint32_t as[BM * AW];
    __shared__ uint32_t bs[BN * AW];

    const int tid  = threadIdx.x;
    const int lane = tid & 31;
    const int wid  = tid >> 5;
    const int wm   = wid & 3;         // 4 m-warps * 32 rows
    const int wn   = wid >> 2;        // 2 n-warps * WN cols
    const int g    = lane >> 2;
    const int q    = lane & 3;
    const int m0   = blockIdx.x * BM;

    float acc[2][NFRAG][4];
#pragma unroll
    for (int mi = 0; mi < 2; mi++)
#pragma unroll
        for (int j = 0; j < NFRAG; j++)
#pragma unroll
            for (int t = 0; t < 4; t++) acc[mi][j][t] = 0.0f;

    for (int k0 = 0; k0 < K; k0 += BK) {
        // ---- stage A tile (BM x BK) into as[m][word], 2 halves per word ----
        if (A_FP32) {
            const float* A = (const float*)Ain;
#pragma unroll
            for (int it = 0; it < 2; it++) {
                int idx = tid + it * 256;       // 512 groups of 4 words
                int m   = idx >> 2;
                int w4  = idx & 3;              // group of 4 words = 8 k-values
                float4 v0 = make_float4(0.f, 0.f, 0.f, 0.f);
                float4 v1 = v0;
                if (m0 + m < M) {
                    const float* p = A + (size_t)(m0 + m) * K + k0 + w4 * 8;
                    v0 = __ldg(reinterpret_cast<const float4*>(p));
                    v1 = __ldg(reinterpret_cast<const float4*>(p + 4));
                }
                int base = m * AW + w4 * 4;
                as[base + 0] = pack_h2(v0.x, v0.y);
                as[base + 1] = pack_h2(v0.z, v0.w);
                as[base + 2] = pack_h2(v1.x, v1.y);
                as[base + 3] = pack_h2(v1.z, v1.w);
            }
        } else {
            const __half* A = (const __half*)Ain;
#pragma unroll
            for (int it = 0; it < 2; it++) {
                int idx = tid + it * 256;       // 512 uint4 (4 words each)
                int m   = idx >> 2;
                int w4  = idx & 3;
                uint4 v = make_uint4(0u, 0u, 0u, 0u);
                if (m0 + m < M)
                    v = __ldg(reinterpret_cast<const uint4*>(A + (size_t)(m0 + m) * K + k0) + w4);
                int base = m * AW + w4 * 4;
                as[base + 0] = v.x;
                as[base + 1] = v.y;
                as[base + 2] = v.z;
                as[base + 3] = v.w;
            }
        }
        // ---- stage B tile (BK x BN) transposed to [n][k-word] with swizzle ----
#pragma unroll
        for (int it = 0; it < (16 * BN) / 256; it++) {
            int i  = tid + it * 256;
            int n  = i % BN;          // coalesced over n
            int kw = i / BN;          // 0..15
            float x0 = __ldg(W + (size_t)(k0 + 2 * kw) * BN + n);
            float x1 = __ldg(W + (size_t)(k0 + 2 * kw + 1) * BN + n);
            int sw = kw ^ ((n >> 3) & 7);
            bs[n * AW + sw] = pack_h2(x0, x1);
        }
        __syncthreads();

        // ---- 2 k16 steps per BK tile ----
#pragma unroll
        for (int kk = 0; kk < BK; kk += 16) {
            const int kwb = (kk >> 1) + q;
            uint32_t a[2][4];
#pragma unroll
            for (int mi = 0; mi < 2; mi++) {
                int r0 = (wm * 32 + mi * 16 + g) * AW;
                int r8 = r0 + 8 * AW;
                a[mi][0] = as[r0 + kwb];
                a[mi][1] = as[r8 + kwb];
                a[mi][2] = as[r0 + kwb + 4];
                a[mi][3] = as[r8 + kwb + 4];
            }
#pragma unroll
            for (int j = 0; j < NFRAG; j++) {
                int n  = wn * WN + 8 * j + g;
                int v  = (n >> 3) & 7;
                int nb = n * AW;
                uint32_t b0 = bs[nb + (kwb ^ v)];
                uint32_t b1 = bs[nb + ((kwb + 4) ^ v)];
#pragma unroll
                for (int mi = 0; mi < 2; mi++) mma_f16(acc[mi][j], a[mi], b0, b1);
            }
        }
        __syncthreads();
    }

    // ---- epilogue: fp32 acc -> fp16 C ----
#pragma unroll
    for (int mi = 0; mi < 2; mi++) {
        int row = m0 + wm * 32 + mi * 16 + g;
#pragma unroll
        for (int j = 0; j < NFRAG; j++) {
            int col = wn * WN + 8 * j + q * 2;
            if (row < M)
                *reinterpret_cast<uint32_t*>(C + (size_t)row * BN + col) =
                    pack_h2(acc[mi][j][0], acc[mi][j][1]);
            if (row + 8 < M)
                *reinterpret_cast<uint32_t*>(C + (size_t)(row + 8) * BN + col) =
                    pack_h2(acc[mi][j][2], acc[mi][j][3]);
        }
    }
}

// ---------------------------------------------------------------------------
// CSR aggregation (fp16 h, fp32 accumulate): warp per destination node.
// res[d] = dinv[d]^2*h[d] + sum_e w_e*h[src_e] + bias ; optional ReLU; fp16 out
// ---------------------------------------------------------------------------
__global__ void agg_csr_f128_h(const __half* __restrict__ h, const int2* __restrict__ csr,
                               const int* __restrict__ rowptr, const float* __restrict__ dinv,
                               const float* __restrict__ bias, __half* __restrict__ out,
                               int n, int e_cnt) {
    int warp = (blockIdx.x * blockDim.x + threadIdx.x) >> 5;
    int lane = threadIdx.x & 31;
    if (warp >= n) return;
    const int d = warp;

    float di = __ldg(dinv + d);
    di *= di;
    uint2 hv = __ldg(reinterpret_cast<const uint2*>(h + (size_t)d * 128) + lane);
    float2 h0 = __half22float2(*reinterpret_cast<__half2*>(&hv.x));
    float2 h1 = __half22float2(*reinterpret_cast<__half2*>(&hv.y));
    float4 b4 = __ldg(reinterpret_cast<const float4*>(bias) + lane);
    float4 acc;
    acc.x = h0.x * di + b4.x;
    acc.y = h0.y * di + b4.y;
    acc.z = h1.x * di + b4.z;
    acc.w = h1.y * di + b4.w;

    int start = __ldg(rowptr + d);
    int end   = (d == n - 1) ? e_cnt : __ldg(rowptr + d + 1);

    for (int base = start; base < end; base += 32) {
        int m = min(32, end - base);
        int2 ew = make_int2(0, 0);
        if (lane < m) ew = __ldg(csr + base + lane);
        for (int j = 0; j < m; j++) {
            int   s = __shfl_sync(0xffffffffu, ew.x, j);
            float w = __int_as_float(__shfl_sync(0xffffffffu, ew.y, j));
            uint2 vv = __ldg(reinterpret_cast<const uint2*>(h + (size_t)s * 128) + lane);
            float2 v0 = __half22float2(*reinterpret_cast<__half2*>(&vv.x));
            float2 v1 = __half22float2(*reinterpret_cast<__half2*>(&vv.y));
            acc.x = fmaf(w, v0.x, acc.x);
            acc.y = fmaf(w, v0.y, acc.y);
            acc.z = fmaf(w, v1.x, acc.z);
            acc.w = fmaf(w, v1.y, acc.w);
        }
    }
    // ReLU + fp16 store
    acc.x = fmaxf(acc.x, 0.f); acc.y = fmaxf(acc.y, 0.f);
    acc.z = fmaxf(acc.z, 0.f); acc.w = fmaxf(acc.w, 0.f);
    uint2 o;
    o.x = pack_h2(acc.x, acc.y);
    o.y = pack_h2(acc.z, acc.w);
    *(reinterpret_cast<uint2*>(out + (size_t)d * 128) + lane) = o;
}

// Final layer: F=64, no ReLU, fp32 output
__global__ void agg_csr_f64_out(const __half* __restrict__ h, const int2* __restrict__ csr,
                                const int* __restrict__ rowptr, const float* __restrict__ dinv,
                                const float* __restrict__ bias, float* __restrict__ out,
                                int n, int e_cnt) {
    int warp = (blockIdx.x * blockDim.x + threadIdx.x) >> 5;
    int lane = threadIdx.x & 31;
    if (warp >= n) return;
    const int d = warp;

    float di = __ldg(dinv + d);
    di *= di;
    uint32_t hv = __ldg(reinterpret_cast<const uint32_t*>(h + (size_t)d * 64) + lane);
    float2 h0 = __half22float2(*reinterpret_cast<__half2*>(&hv));
    float2 b2 = __ldg(reinterpret_cast<const float2*>(bias) + lane);
    float2 acc;
    acc.x = h0.x * di + b2.x;
    acc.y = h0.y * di + b2.y;

    int start = __ldg(rowptr + d);
    int end   = (d == n - 1) ? e_cnt : __ldg(rowptr + d + 1);

    for (int base = start; base < end; base += 32) {
        int m = min(32, end - base);
        int2 ew = make_int2(0, 0);
        if (lane < m) ew = __ldg(csr + base + lane);
        for (int j = 0; j < m; j++) {
            int   s = __shfl_sync(0xffffffffu, ew.x, j);
            float w = __int_as_float(__shfl_sync(0xffffffffu, ew.y, j));
            uint32_t vv = __ldg(reinterpret_cast<const uint32_t*>(h + (size_t)s * 64) + lane);
            float2 v0 = __half22float2(*reinterpret_cast<__half2*>(&vv));
            acc.x = fmaf(w, v0.x, acc.x);
            acc.y = fmaf(w, v0.y, acc.y);
        }
    }
    *(reinterpret_cast<float2*>(out + (size_t)d * 64) + lane) = acc;
}

// ---------------------------------------------------------------------------
// Launcher
// ---------------------------------------------------------------------------
extern "C" void kernel_launch(void* const* d_in, const int* in_sizes, int n_in,
                              void* d_out, int out_size) {
    const float* x   = (const float*)d_in[0];
    const int*   ei  = (const int*)d_in[1];     // int32 edge_index [2, E]
    const float* W1  = (const float*)d_in[2];
    const float* b1  = (const float*)d_in[3];
    const float* W2  = (const float*)d_in[4];
    const float* b2  = (const float*)d_in[5];
    const float* W3  = (const float*)d_in[6];
    const float* b3  = (const float*)d_in[7];
    float*       out = (float*)d_out;

    const int E = in_sizes[1] / 2;      // 1,600,000
    const int N = in_sizes[0] / FEAT;   // 100,000

    void *pA, *pB, *pC, *pDinv, *pDeg, *pRow, *pCur, *pBS, *pCsr;
    cudaGetSymbolAddress(&pA, g_hA);
    cudaGetSymbolAddress(&pB, g_hB);
    cudaGetSymbolAddress(&pC, g_hC);
    cudaGetSymbolAddress(&pDinv, g_dinv);
    cudaGetSymbolAddress(&pDeg, g_deg);
    cudaGetSymbolAddress(&pRow, g_rowptr);
    cudaGetSymbolAddress(&pCur, g_cursor);
    cudaGetSymbolAddress(&pBS, g_blocksum);
    cudaGetSymbolAddress(&pCsr, g_csr);
    __half* hA    = (__half*)pA;
    __half* hB    = (__half*)pB;
    __half* hC    = (__half*)pC;
    float* dinv   = (float*)pDinv;
    int*   deg    = (int*)pDeg;
    int*   rowptr = (int*)pRow;
    int*   cursor = (int*)pCur;
    int*   bsum   = (int*)pBS;
    int2*  csr    = (int2*)pCsr;

    const int T  = 256;
    const int gN = (N + T - 1) / T;
    const int gE = (E + T - 1) / T;
    const int gM = (N + 127) / 128;                     // GEMM row blocks
    const int gW = ((size_t)N * 32 + T - 1) / T;        // warp per node

    // ---- prep: degree, dinv, CSR ----
    k_deg_init<<<gN, T>>>(deg, N);
    k_deg_count<<<gE, T>>>(ei, deg, E);
    k_dinv<<<gN, T>>>(deg, dinv, N);
    k_scan_block<<<SCAN_NB, 256>>>(deg, rowptr, bsum, N);
    k_scan_mid<<<1, 512>>>(bsum, SCAN_NB);
    k_scan_add<<<gN, T>>>(rowptr, cursor, bsum, N);
    k_scatter<<<gE, T>>>(ei, dinv, cursor, csr, E);

    // ---- layer 1: x@W1 -> hA ; csr-agg(hA)+b1, ReLU -> hB ----
    gemm_f16_kernel<128, true><<<gM, 256>>>(x, W1, hA, N, FEAT);
    agg_csr_f128_h<<<gW, T>>>(hA, csr, rowptr, dinv, b1, hB, N, E);

    // ---- layer 2: hB@W2 -> hA ; csr-agg(hA)+b2, ReLU -> hB ----
    gemm_f16_kernel<128, false><<<gM, 256>>>(hB, W2, hA, N, HID);
    agg_csr_f128_h<<<gW, T>>>(hA, csr, rowptr, dinv, b2, hB, N, E);

    // ---- layer 3: hB@W3 -> hC ; csr-agg(hC)+b3 -> out (fp32) ----
    gemm_f16_kernel<64, false><<<gM, 256>>>(hB, W3, hC, N, HID);
    agg_csr_f64_out<<<gW, T>>>(hC, csr, rowptr, dinv, b3, out, N, E);
}

// round 7
// speedup vs baseline: 3.5553x; 1.0528x over previous
#include <cuda_runtime.h>
#include <cuda_fp16.h>
#include <cstdint>
#include <cstddef>

// Problem constants (fixed by the dataset)
#define NN   100000
#define FEAT 256
#define HID  128
#define OUTF 64
#define EE   1600000
#define SCAN_NB ((NN + 255) / 256)   // 391

// ---------------------------------------------------------------------------
// Static device scratch (allocation-free rule: __device__ globals)
// ---------------------------------------------------------------------------
__device__ __align__(16) __half g_hX[(size_t)NN * FEAT];  // 51.2 MB (x in fp16)
__device__ __align__(16) __half g_hA[(size_t)NN * HID];   // 25.6 MB (GEMM out)
__device__ __align__(16) __half g_hB[(size_t)NN * HID];   // 25.6 MB (agg out)
__device__ __align__(16) __half g_hC[(size_t)NN * OUTF];  // 12.8 MB
__device__ __align__(16) __half g_Wt1[FEAT * HID];        // W1^T fp16 [n][k]
__device__ __align__(16) __half g_Wt2[HID * HID];
__device__ __align__(16) __half g_Wt3[HID * OUTF];
__device__ __align__(16) float  g_dinv[NN];
__device__ __align__(16) int    g_deg[NN];
__device__ __align__(16) int    g_rowptr[NN];
__device__ __align__(16) int    g_cursor[NN];
__device__ __align__(16) int    g_blocksum[512];
__device__ __align__(16) int2   g_csr[EE];                // {src, norm-as-int}

// ---------------------------------------------------------------------------
// Helpers
// ---------------------------------------------------------------------------
__device__ __forceinline__ uint32_t smem_u32(const void* p) {
    uint32_t a;
    asm("{ .reg .u64 t; cvta.to.shared.u64 t, %1; cvt.u32.u64 %0, t; }"
        : "=r"(a) : "l"(p));
    return a;
}

__device__ __forceinline__ uint32_t pack_h2(float x0, float x1) {
    __half2 h = __floats2half2_rn(x0, x1);
    return *reinterpret_cast<uint32_t*>(&h);
}

#define SW128(x) ((x) ^ (((x) >> 3) & 0x70))

__device__ __forceinline__ void cp16(uint32_t dst, const void* src) {
    asm volatile("cp.async.cg.shared.global [%0], [%1], 16;"
                 :: "r"(dst), "l"(src) : "memory");
}
#define CP_COMMIT() asm volatile("cp.async.commit_group;" ::: "memory")
#define CP_WAIT(n)  asm volatile("cp.async.wait_group %0;" :: "n"(n) : "memory")

#define LDSM_X4(r, addr)                                                      \
    asm volatile("ldmatrix.sync.aligned.m8n8.x4.shared.b16 {%0,%1,%2,%3}, [%4];" \
        : "=r"((r)[0]), "=r"((r)[1]), "=r"((r)[2]), "=r"((r)[3]) : "r"(addr))

__device__ __forceinline__ void mma_f16(float* c, const uint32_t* a, uint32_t b0, uint32_t b1) {
    asm volatile(
        "mma.sync.aligned.m16n8k16.row.col.f32.f16.f16.f32 "
        "{%0,%1,%2,%3}, {%4,%5,%6,%7}, {%8,%9}, {%0,%1,%2,%3};"
        : "+f"(c[0]), "+f"(c[1]), "+f"(c[2]), "+f"(c[3])
        : "r"(a[0]), "r"(a[1]), "r"(a[2]), "r"(a[3]), "r"(b0), "r"(b1));
}

// ---------------------------------------------------------------------------
// Prep: degree, dinv, CSR build (histogram -> scan -> scatter)
// edge_index is int32 (JAX x64 disabled -> int64 request silently becomes int32)
// ---------------------------------------------------------------------------
__global__ void k_deg_init(int* deg, int n) {
    int i = blockIdx.x * blockDim.x + threadIdx.x;
    if (i < n) deg[i] = 1;  // self-loop
}

__global__ void k_deg_count(const int* __restrict__ ei, int* deg, int e_cnt) {
    int e = blockIdx.x * blockDim.x + threadIdx.x;
    if (e < e_cnt) atomicAdd(deg + ei[e_cnt + e], 1);
}

__global__ void k_dinv(const int* __restrict__ deg, float* dinv, int n) {
    int i = blockIdx.x * blockDim.x + threadIdx.x;
    if (i < n) dinv[i] = rsqrtf((float)deg[i]);
}

__global__ void k_scan_block(const int* __restrict__ deg, int* rowptr, int* blocksum, int n) {
    __shared__ int s[256];
    int i = blockIdx.x * 256 + threadIdx.x;
    int v = (i < n) ? deg[i] - 1 : 0;
    s[threadIdx.x] = v;
    __syncthreads();
#pragma unroll
    for (int off = 1; off < 256; off <<= 1) {
        int t = (threadIdx.x >= off) ? s[threadIdx.x - off] : 0;
        __syncthreads();
        s[threadIdx.x] += t;
        __syncthreads();
    }
    if (i < n) rowptr[i] = s[threadIdx.x] - v;  // exclusive
    if (threadIdx.x == 255) blocksum[blockIdx.x] = s[255];
}

__global__ void k_scan_mid(int* blocksum, int nb) {
    __shared__ int s[512];
    int i = threadIdx.x;
    int v = (i < nb) ? blocksum[i] : 0;
    s[i] = v;
    __syncthreads();
#pragma unroll
    for (int off = 1; off < 512; off <<= 1) {
        int t = (i >= off) ? s[i - off] : 0;
        __syncthreads();
        s[i] += t;
        __syncthreads();
    }
    if (i < nb) blocksum[i] = s[i] - v;  // exclusive
}

__global__ void k_scan_add(int* rowptr, int* cursor, const int* __restrict__ blocksum, int n) {
    int i = blockIdx.x * blockDim.x + threadIdx.x;
    if (i < n) {
        int r = rowptr[i] + blocksum[i >> 8];
        rowptr[i] = r;
        cursor[i] = r;
    }
}

__global__ void k_scatter(const int* __restrict__ ei, const float* __restrict__ dinv,
                          int* cursor, int2* __restrict__ csr, int e_cnt) {
    int e = blockIdx.x * blockDim.x + threadIdx.x;
    if (e >= e_cnt) return;
    int s = ei[e];
    int d = ei[e_cnt + e];
    float w = __ldg(dinv + s) * __ldg(dinv + d);
    int pos = atomicAdd(cursor + d, 1);
    csr[pos] = make_int2(s, __float_as_int(w));
}

// ---------------------------------------------------------------------------
// Preconvert: x fp32 -> fp16 ; W [k][n] fp32 -> Wt [n][k] fp16
// ---------------------------------------------------------------------------
__global__ void k_x2h(const float* __restrict__ x, __half* __restrict__ hx, int n4) {
    int i = blockIdx.x * blockDim.x + threadIdx.x;
    if (i >= n4) return;
    float4 v = __ldg(reinterpret_cast<const float4*>(x) + i);
    uint2 o;
    o.x = pack_h2(v.x, v.y);
    o.y = pack_h2(v.z, v.w);
    reinterpret_cast<uint2*>(hx)[i] = o;
}

__global__ void k_w2h_t(const float* __restrict__ W, __half* __restrict__ Wt, int K, int Nc) {
    int i = blockIdx.x * blockDim.x + threadIdx.x;
    if (i >= K * Nc) return;
    int k = i / Nc, n = i % Nc;
    Wt[(size_t)n * K + k] = __float2half_rn(__ldg(W + i));
}

// ---------------------------------------------------------------------------
// HMMA GEMM (fp16 in, fp32 acc, fp16 out), cp.async double buffer + ldmatrix.
// C[M,BN] = A[M,K_DIM] @ B, with B given pre-transposed fp16 Bt[n][k].
// BM=128, BK=64, 8 warps: 4 m-warps (32 rows) x 2 n-warps (BN/2 cols).
// ---------------------------------------------------------------------------
template <int K_DIM, int BN>
__global__ void __launch_bounds__(256, 2)
gemm_hmma(const __half* __restrict__ A, const __half* __restrict__ Bt,
          __half* __restrict__ C, int M) {
    constexpr int BM = 128;
    constexpr int BK = 64;
    constexpr int NIT = K_DIM / BK;
    constexpr int WN = BN / 2;
    constexpr int NFRAG = WN / 8;
    constexpr int ABYTES = BM * BK * 2;   // 16 KB
    constexpr int BBYTES = BN * BK * 2;   // 16/8 KB

    extern __shared__ char dyn[];
    const uint32_t dynb = smem_u32(dyn);
    const uint32_t base = (dynb + 1023) & ~1023u;         // 128B+ align for swizzle
    const uint32_t sa[2] = { base, base + ABYTES };
    const uint32_t sb[2] = { base + 2 * ABYTES, base + 2 * ABYTES + BBYTES };

    const int tid  = threadIdx.x;
    const int lane = tid & 31;
    const int wid  = tid >> 5;
    const int wm   = wid & 3;
    const int wn   = wid >> 2;
    const int g    = lane >> 2;
    const int q    = lane & 3;
    const int m0   = blockIdx.x * BM;

    // ldmatrix per-lane geometry
    const int sub = lane >> 3;
    const int l7  = lane & 7;
    const int a_mr   = wm * 32 + (sub & 1) * 8 + l7;      // + mi*16
    const int a_koff = (sub >> 1) * 8;
    const int b_nr   = wn * WN + ((sub >> 1) & 1) * 8 + l7;  // + j2*16
    const int b_koff = (sub & 1) * 8;

    float acc[2][NFRAG][4];
#pragma unroll
    for (int mi = 0; mi < 2; mi++)
#pragma unroll
        for (int j = 0; j < NFRAG; j++)
#pragma unroll
            for (int t = 0; t < 4; t++) acc[mi][j][t] = 0.0f;

    // ---- staging lambda-ish macro: copy stage `it` into buffer `it&1` ----
    auto stage = [&](int it) {
        int k0 = it * BK;
        int bufi = it & 1;
        // A: 1024 16B-chunks (128 rows x 8 groups)
#pragma unroll
        for (int c = tid; c < BM * 8; c += 256) {
            int row = c >> 3, grp = c & 7;
            int gr = m0 + row;
            if (gr >= M) gr = M - 1;
            cp16(sa[bufi] + SW128(row * 128 + grp * 16),
                 A + (size_t)gr * K_DIM + k0 + grp * 8);
        }
        // B: BN*8 chunks
#pragma unroll
        for (int c = tid; c < BN * 8; c += 256) {
            int n = c >> 3, grp = c & 7;
            cp16(sb[bufi] + SW128(n * 128 + grp * 16),
                 Bt + (size_t)n * K_DIM + k0 + grp * 8);
        }
    };

    stage(0);
    CP_COMMIT();

    for (int it = 0; it < NIT; it++) {
        if (it + 1 < NIT) {
            stage(it + 1);
            CP_COMMIT();
            CP_WAIT(1);
        } else {
            CP_WAIT(0);
        }
        __syncthreads();

        const uint32_t abuf = sa[it & 1];
        const uint32_t bbuf = sb[it & 1];

#pragma unroll
        for (int kk = 0; kk < BK; kk += 16) {
            uint32_t a[2][4];
#pragma unroll
            for (int mi = 0; mi < 2; mi++) {
                uint32_t addr = abuf + SW128((a_mr + mi * 16) * 128 + (kk + a_koff) * 2);
                LDSM_X4(a[mi], addr);
            }
#pragma unroll
            for (int j2 = 0; j2 < NFRAG / 2; j2++) {
                uint32_t b[4];
                uint32_t addr = bbuf + SW128((b_nr + j2 * 16) * 128 + (kk + b_koff) * 2);
                LDSM_X4(b, addr);
                mma_f16(acc[0][2 * j2],     a[0], b[0], b[1]);
                mma_f16(acc[1][2 * j2],     a[1], b[0], b[1]);
                mma_f16(acc[0][2 * j2 + 1], a[0], b[2], b[3]);
                mma_f16(acc[1][2 * j2 + 1], a[1], b[2], b[3]);
            }
        }
        __syncthreads();
    }

    // ---- epilogue: fp32 acc -> fp16 C ----
#pragma unroll
    for (int mi = 0; mi < 2; mi++) {
        int row = m0 + wm * 32 + mi * 16 + g;
#pragma unroll
        for (int j = 0; j < NFRAG; j++) {
            int col = wn * WN + 8 * j + q * 2;
            if (row < M)
                *reinterpret_cast<uint32_t*>(C + (size_t)row * BN + col) =
                    pack_h2(acc[mi][j][0], acc[mi][j][1]);
            if (row + 8 < M)
                *reinterpret_cast<uint32_t*>(C + (size_t)(row + 8) * BN + col) =
                    pack_h2(acc[mi][j][2], acc[mi][j][3]);
        }
    }
}

// ---------------------------------------------------------------------------
// CSR aggregation (fp16 h, fp32 accumulate): warp per destination node.
// res[d] = dinv[d]^2*h[d] + sum_e w_e*h[src_e] + bias ; optional ReLU; fp16 out
// ---------------------------------------------------------------------------
__global__ void agg_csr_f128_h(const __half* __restrict__ h, const int2* __restrict__ csr,
                               const int* __restrict__ rowptr, const float* __restrict__ dinv,
                               const float* __restrict__ bias, __half* __restrict__ out,
                               int n, int e_cnt) {
    int warp = (blockIdx.x * blockDim.x + threadIdx.x) >> 5;
    int lane = threadIdx.x & 31;
    if (warp >= n) return;
    const int d = warp;

    float di = __ldg(dinv + d);
    di *= di;
    uint2 hv = __ldg(reinterpret_cast<const uint2*>(h + (size_t)d * 128) + lane);
    float2 h0 = __half22float2(*reinterpret_cast<__half2*>(&hv.x));
    float2 h1 = __half22float2(*reinterpret_cast<__half2*>(&hv.y));
    float4 b4 = __ldg(reinterpret_cast<const float4*>(bias) + lane);
    float4 acc;
    acc.x = h0.x * di + b4.x;
    acc.y = h0.y * di + b4.y;
    acc.z = h1.x * di + b4.z;
    acc.w = h1.y * di + b4.w;

    int start = __ldg(rowptr + d);
    int end   = (d == n - 1) ? e_cnt : __ldg(rowptr + d + 1);

    for (int base = start; base < end; base += 32) {
        int m = min(32, end - base);
        int2 ew = make_int2(0, 0);
        if (lane < m) ew = __ldg(csr + base + lane);
        for (int j = 0; j < m; j++) {
            int   s = __shfl_sync(0xffffffffu, ew.x, j);
            float w = __int_as_float(__shfl_sync(0xffffffffu, ew.y, j));
            uint2 vv = __ldg(reinterpret_cast<const uint2*>(h + (size_t)s * 128) + lane);
            float2 v0 = __half22float2(*reinterpret_cast<__half2*>(&vv.x));
            float2 v1 = __half22float2(*reinterpret_cast<__half2*>(&vv.y));
            acc.x = fmaf(w, v0.x, acc.x);
            acc.y = fmaf(w, v0.y, acc.y);
            acc.z = fmaf(w, v1.x, acc.z);
            acc.w = fmaf(w, v1.y, acc.w);
        }
    }
    acc.x = fmaxf(acc.x, 0.f); acc.y = fmaxf(acc.y, 0.f);
    acc.z = fmaxf(acc.z, 0.f); acc.w = fmaxf(acc.w, 0.f);
    uint2 o;
    o.x = pack_h2(acc.x, acc.y);
    o.y = pack_h2(acc.z, acc.w);
    *(reinterpret_cast<uint2*>(out + (size_t)d * 128) + lane) = o;
}

// Final layer: F=64, no ReLU, fp32 output
__global__ void agg_csr_f64_out(const __half* __restrict__ h, const int2* __restrict__ csr,
                                const int* __restrict__ rowptr, const float* __restrict__ dinv,
                                const float* __restrict__ bias, float* __restrict__ out,
                                int n, int e_cnt) {
    int warp = (blockIdx.x * blockDim.x + threadIdx.x) >> 5;
    int lane = threadIdx.x & 31;
    if (warp >= n) return;
    const int d = warp;

    float di = __ldg(dinv + d);
    di *= di;
    uint32_t hv = __ldg(reinterpret_cast<const uint32_t*>(h + (size_t)d * 64) + lane);
    float2 h0 = __half22float2(*reinterpret_cast<__half2*>(&hv));
    float2 b2 = __ldg(reinterpret_cast<const float2*>(bias) + lane);
    float2 acc;
    acc.x = h0.x * di + b2.x;
    acc.y = h0.y * di + b2.y;

    int start = __ldg(rowptr + d);
    int end   = (d == n - 1) ? e_cnt : __ldg(rowptr + d + 1);

    for (int base = start; base < end; base += 32) {
        int m = min(32, end - base);
        int2 ew = make_int2(0, 0);
        if (lane < m) ew = __ldg(csr + base + lane);
        for (int j = 0; j < m; j++) {
            int   s = __shfl_sync(0xffffffffu, ew.x, j);
            float w = __int_as_float(__shfl_sync(0xffffffffu, ew.y, j));
            uint32_t vv = __ldg(reinterpret_cast<const uint32_t*>(h + (size_t)s * 64) + lane);
            float2 v0 = __half22float2(*reinterpret_cast<__half2*>(&vv));
            acc.x = fmaf(w, v0.x, acc.x);
            acc.y = fmaf(w, v0.y, acc.y);
        }
    }
    *(reinterpret_cast<float2*>(out + (size_t)d * 64) + lane) = acc;
}

// ---------------------------------------------------------------------------
// Launcher
// ---------------------------------------------------------------------------
extern "C" void kernel_launch(void* const* d_in, const int* in_sizes, int n_in,
                              void* d_out, int out_size) {
    const float* x   = (const float*)d_in[0];
    const int*   ei  = (const int*)d_in[1];     // int32 edge_index [2, E]
    const float* W1  = (const float*)d_in[2];
    const float* b1  = (const float*)d_in[3];
    const float* W2  = (const float*)d_in[4];
    const float* b2  = (const float*)d_in[5];
    const float* W3  = (const float*)d_in[6];
    const float* b3  = (const float*)d_in[7];
    float*       out = (float*)d_out;

    const int E = in_sizes[1] / 2;      // 1,600,000
    const int N = in_sizes[0] / FEAT;   // 100,000

    void *pX, *pA, *pB, *pC, *pW1, *pW2, *pW3;
    void *pDinv, *pDeg, *pRow, *pCur, *pBS, *pCsr;
    cudaGetSymbolAddress(&pX, g_hX);
    cudaGetSymbolAddress(&pA, g_hA);
    cudaGetSymbolAddress(&pB, g_hB);
    cudaGetSymbolAddress(&pC, g_hC);
    cudaGetSymbolAddress(&pW1, g_Wt1);
    cudaGetSymbolAddress(&pW2, g_Wt2);
    cudaGetSymbolAddress(&pW3, g_Wt3);
    cudaGetSymbolAddress(&pDinv, g_dinv);
    cudaGetSymbolAddress(&pDeg, g_deg);
    cudaGetSymbolAddress(&pRow, g_rowptr);
    cudaGetSymbolAddress(&pCur, g_cursor);
    cudaGetSymbolAddress(&pBS, g_blocksum);
    cudaGetSymbolAddress(&pCsr, g_csr);
    __half* hX    = (__half*)pX;
    __half* hA    = (__half*)pA;
    __half* hB    = (__half*)pB;
    __half* hC    = (__half*)pC;
    __half* Wt1   = (__half*)pW1;
    __half* Wt2   = (__half*)pW2;
    __half* Wt3   = (__half*)pW3;
    float* dinv   = (float*)pDinv;
    int*   deg    = (int*)pDeg;
    int*   rowptr = (int*)pRow;
    int*   cursor = (int*)pCur;
    int*   bsum   = (int*)pBS;
    int2*  csr    = (int2*)pCsr;

    const int T  = 256;
    const int gN = (N + T - 1) / T;
    const int gE = (E + T - 1) / T;
    const int gM = (N + 127) / 128;                     // GEMM row blocks
    const int gW = ((size_t)N * 32 + T - 1) / T;        // warp per node
    const int gX = ((N * FEAT / 4) + T - 1) / T;

    // dyn smem: 2*(A 16K + B 16K/8K) + 1K align
    const int smem128 = 2 * (16384 + 16384) + 1024;     // 66.5 KB
    const int smem64  = 2 * (16384 + 8192) + 1024;      // 50 KB

    static bool attr_done = false;
    if (!attr_done) {
        cudaFuncSetAttribute(gemm_hmma<256, 128>,
                             cudaFuncAttributeMaxDynamicSharedMemorySize, smem128);
        cudaFuncSetAttribute(gemm_hmma<128, 128>,
                             cudaFuncAttributeMaxDynamicSharedMemorySize, smem128);
        cudaFuncSetAttribute(gemm_hmma<128, 64>,
                             cudaFuncAttributeMaxDynamicSharedMemorySize, smem64);
        attr_done = true;
    }

    // ---- prep: degree, dinv, CSR ; preconvert x & weights ----
    k_deg_init<<<gN, T>>>(deg, N);
    k_deg_count<<<gE, T>>>(ei, deg, E);
    k_dinv<<<gN, T>>>(deg, dinv, N);
    k_scan_block<<<SCAN_NB, 256>>>(deg, rowptr, bsum, N);
    k_scan_mid<<<1, 512>>>(bsum, SCAN_NB);
    k_scan_add<<<gN, T>>>(rowptr, cursor, bsum, N);
    k_scatter<<<gE, T>>>(ei, dinv, cursor, csr, E);
    k_x2h<<<gX, T>>>(x, hX, N * FEAT / 4);
    k_w2h_t<<<(FEAT * HID + T - 1) / T, T>>>(W1, Wt1, FEAT, HID);
    k_w2h_t<<<(HID * HID + T - 1) / T, T>>>(W2, Wt2, HID, HID);
    k_w2h_t<<<(HID * OUTF + T - 1) / T, T>>>(W3, Wt3, HID, OUTF);

    // ---- layer 1: hX@W1 -> hA ; csr-agg(hA)+b1, ReLU -> hB ----
    gemm_hmma<256, 128><<<gM, 256, smem128>>>(hX, Wt1, hA, N);
    agg_csr_f128_h<<<gW, T>>>(hA, csr, rowptr, dinv, b1, hB, N, E);

    // ---- layer 2: hB@W2 -> hA ; csr-agg(hA)+b2, ReLU -> hB ----
    gemm_hmma<128, 128><<<gM, 256, smem128>>>(hB, Wt2, hA, N);
    agg_csr_f128_h<<<gW, T>>>(hA, csr, rowptr, dinv, b2, hB, N, E);

    // ---- layer 3: hB@W3 -> hC ; csr-agg(hC)+b3 -> out (fp32) ----
    gemm_hmma<128, 64><<<gM, 256, smem64>>>(hB, Wt3, hC, N);
    agg_csr_f64_out<<<gW, T>>>(hC, csr, rowptr, dinv, b3, out, N, E);
}

// round 8
// speedup vs baseline: 3.5684x; 1.0037x over previous
#include <cuda_runtime.h>
#include <cuda_fp16.h>
#include <cstdint>
#include <cstddef>

// Problem constants (fixed by the dataset)
#define NN   100000
#define FEAT 256
#define HID  128
#define OUTF 64
#define EE   1600000
#define SCAN_NB ((NN + 255) / 256)   // 391

// ---------------------------------------------------------------------------
// Static device scratch (allocation-free rule: __device__ globals)
// ---------------------------------------------------------------------------
__device__ __align__(16) __half g_hX[(size_t)NN * FEAT];  // 51.2 MB (x in fp16)
__device__ __align__(16) __half g_hA[(size_t)NN * HID];   // 25.6 MB (GEMM out)
__device__ __align__(16) __half g_hB[(size_t)NN * HID];   // 25.6 MB (agg out)
__device__ __align__(16) __half g_hC[(size_t)NN * OUTF];  // 12.8 MB
__device__ __align__(16) __half g_Wt1[FEAT * HID];        // W1^T fp16 [n][k]
__device__ __align__(16) __half g_Wt2[HID * HID];
__device__ __align__(16) __half g_Wt3[HID * OUTF];
__device__ __align__(16) float  g_dinv[NN];
__device__ __align__(16) int    g_deg[NN];
__device__ __align__(16) int    g_rowptr[NN];
__device__ __align__(16) int    g_cursor[NN];
__device__ __align__(16) int    g_blocksum[512];
__device__ __align__(16) int2   g_csr[EE];                // {src, norm-as-int}

// ---------------------------------------------------------------------------
// Helpers
// ---------------------------------------------------------------------------
__device__ __forceinline__ uint32_t smem_u32(const void* p) {
    uint32_t a;
    asm("{ .reg .u64 t; cvta.to.shared.u64 t, %1; cvt.u32.u64 %0, t; }"
        : "=r"(a) : "l"(p));
    return a;
}

__device__ __forceinline__ uint32_t pack_h2(float x0, float x1) {
    __half2 h = __floats2half2_rn(x0, x1);
    return *reinterpret_cast<uint32_t*>(&h);
}

#define SW128(x) ((x) ^ (((x) >> 3) & 0x70))

__device__ __forceinline__ void cp16(uint32_t dst, const void* src) {
    asm volatile("cp.async.cg.shared.global [%0], [%1], 16;"
                 :: "r"(dst), "l"(src) : "memory");
}
#define CP_COMMIT() asm volatile("cp.async.commit_group;" ::: "memory")
#define CP_WAIT(n)  asm volatile("cp.async.wait_group %0;" :: "n"(n) : "memory")

#define LDSM_X4(r, addr)                                                      \
    asm volatile("ldmatrix.sync.aligned.m8n8.x4.shared.b16 {%0,%1,%2,%3}, [%4];" \
        : "=r"((r)[0]), "=r"((r)[1]), "=r"((r)[2]), "=r"((r)[3]) : "r"(addr))

__device__ __forceinline__ void mma_f16(float* c, const uint32_t* a, uint32_t b0, uint32_t b1) {
    asm volatile(
        "mma.sync.aligned.m16n8k16.row.col.f32.f16.f16.f32 "
        "{%0,%1,%2,%3}, {%4,%5,%6,%7}, {%8,%9}, {%0,%1,%2,%3};"
        : "+f"(c[0]), "+f"(c[1]), "+f"(c[2]), "+f"(c[3])
        : "r"(a[0]), "r"(a[1]), "r"(a[2]), "r"(a[3]), "r"(b0), "r"(b1));
}

// ---------------------------------------------------------------------------
// Prep kernels. edge_index is int32.
// ---------------------------------------------------------------------------
__global__ void k_deg_init(int* deg, int n) {
    int i = blockIdx.x * blockDim.x + threadIdx.x;
    if (i < n) deg[i] = 1;  // self-loop
}

__global__ void k_deg_count(const int* __restrict__ ei, int* deg, int e_cnt) {
    int e = blockIdx.x * blockDim.x + threadIdx.x;
    if (e < e_cnt) atomicAdd(deg + ei[e_cnt + e], 1);
}

// scan_block also emits dinv (fused former k_dinv)
__global__ void k_scan_block(const int* __restrict__ deg, int* rowptr, int* blocksum,
                             float* dinv, int n) {
    __shared__ int s[256];
    int i = blockIdx.x * 256 + threadIdx.x;
    int dv = (i < n) ? deg[i] : 1;
    if (i < n) dinv[i] = rsqrtf((float)dv);
    int v = (i < n) ? dv - 1 : 0;
    s[threadIdx.x] = v;
    __syncthreads();
#pragma unroll
    for (int off = 1; off < 256; off <<= 1) {
        int t = (threadIdx.x >= off) ? s[threadIdx.x - off] : 0;
        __syncthreads();
        s[threadIdx.x] += t;
        __syncthreads();
    }
    if (i < n) rowptr[i] = s[threadIdx.x] - v;  // exclusive
    if (threadIdx.x == 255) blocksum[blockIdx.x] = s[255];
}

__global__ void k_scan_mid(int* blocksum, int nb) {
    __shared__ int s[512];
    int i = threadIdx.x;
    int v = (i < nb) ? blocksum[i] : 0;
    s[i] = v;
    __syncthreads();
#pragma unroll
    for (int off = 1; off < 512; off <<= 1) {
        int t = (i >= off) ? s[i - off] : 0;
        __syncthreads();
        s[i] += t;
        __syncthreads();
    }
    if (i < nb) blocksum[i] = s[i] - v;  // exclusive
}

__global__ void k_scan_add(int* rowptr, int* cursor, const int* __restrict__ blocksum, int n) {
    int i = blockIdx.x * blockDim.x + threadIdx.x;
    if (i < n) {
        int r = rowptr[i] + blocksum[i >> 8];
        rowptr[i] = r;
        cursor[i] = r;
    }
}

__global__ void k_scatter(const int* __restrict__ ei, const float* __restrict__ dinv,
                          int* cursor, int2* __restrict__ csr, int e_cnt) {
    int e = blockIdx.x * blockDim.x + threadIdx.x;
    if (e >= e_cnt) return;
    int s = ei[e];
    int d = ei[e_cnt + e];
    float w = __ldg(dinv + s) * __ldg(dinv + d);
    int pos = atomicAdd(cursor + d, 1);
    csr[pos] = make_int2(s, __float_as_int(w));
}

// ---------------------------------------------------------------------------
// Preconvert: x fp32 -> fp16 ; W [k][n] fp32 -> Wt [n][k] fp16
// ---------------------------------------------------------------------------
__global__ void k_x2h(const float* __restrict__ x, __half* __restrict__ hx, int n4) {
    int i = blockIdx.x * blockDim.x + threadIdx.x;
    if (i >= n4) return;
    float4 v = __ldg(reinterpret_cast<const float4*>(x) + i);
    uint2 o;
    o.x = pack_h2(v.x, v.y);
    o.y = pack_h2(v.z, v.w);
    reinterpret_cast<uint2*>(hx)[i] = o;
}

__global__ void k_w2h_t(const float* __restrict__ W, __half* __restrict__ Wt, int K, int Nc) {
    int i = blockIdx.x * blockDim.x + threadIdx.x;
    if (i >= K * Nc) return;
    int k = i / Nc, n = i % Nc;
    Wt[(size_t)n * K + k] = __float2half_rn(__ldg(W + i));
}

// ---------------------------------------------------------------------------
// HMMA GEMM (fp16 in, fp32 acc, fp16 out), cp.async double buffer + ldmatrix.
// C[M,BN] = A[M,K_DIM] @ B, with B given pre-transposed fp16 Bt[n][k].
// BM=128, BK=64, 8 warps: 4 m-warps (32 rows) x 2 n-warps (BN/2 cols).
// ---------------------------------------------------------------------------
template <int K_DIM, int BN>
__global__ void __launch_bounds__(256, 2)
gemm_hmma(const __half* __restrict__ A, const __half* __restrict__ Bt,
          __half* __restrict__ C, int M) {
    constexpr int BM = 128;
    constexpr int BK = 64;
    constexpr int NIT = K_DIM / BK;
    constexpr int WN = BN / 2;
    constexpr int NFRAG = WN / 8;
    constexpr int ABYTES = BM * BK * 2;   // 16 KB
    constexpr int BBYTES = BN * BK * 2;   // 16/8 KB

    extern __shared__ char dyn[];
    const uint32_t dynb = smem_u32(dyn);
    const uint32_t base = (dynb + 1023) & ~1023u;
    const uint32_t sa[2] = { base, base + ABYTES };
    const uint32_t sb[2] = { base + 2 * ABYTES, base + 2 * ABYTES + BBYTES };

    const int tid  = threadIdx.x;
    const int lane = tid & 31;
    const int wid  = tid >> 5;
    const int wm   = wid & 3;
    const int wn   = wid >> 2;
    const int g    = lane >> 2;
    const int q    = lane & 3;
    const int m0   = blockIdx.x * BM;

    const int sub = lane >> 3;
    const int l7  = lane & 7;
    const int a_mr   = wm * 32 + (sub & 1) * 8 + l7;
    const int a_koff = (sub >> 1) * 8;
    const int b_nr   = wn * WN + ((sub >> 1) & 1) * 8 + l7;
    const int b_koff = (sub & 1) * 8;

    float acc[2][NFRAG][4];
#pragma unroll
    for (int mi = 0; mi < 2; mi++)
#pragma unroll
        for (int j = 0; j < NFRAG; j++)
#pragma unroll
            for (int t = 0; t < 4; t++) acc[mi][j][t] = 0.0f;

    auto stage = [&](int it) {
        int k0 = it * BK;
        int bufi = it & 1;
#pragma unroll
        for (int c = tid; c < BM * 8; c += 256) {
            int row = c >> 3, grp = c & 7;
            int gr = m0 + row;
            if (gr >= M) gr = M - 1;
            cp16(sa[bufi] + SW128(row * 128 + grp * 16),
                 A + (size_t)gr * K_DIM + k0 + grp * 8);
        }
#pragma unroll
        for (int c = tid; c < BN * 8; c += 256) {
            int n = c >> 3, grp = c & 7;
            cp16(sb[bufi] + SW128(n * 128 + grp * 16),
                 Bt + (size_t)n * K_DIM + k0 + grp * 8);
        }
    };

    stage(0);
    CP_COMMIT();

    for (int it = 0; it < NIT; it++) {
        if (it + 1 < NIT) {
            stage(it + 1);
            CP_COMMIT();
            CP_WAIT(1);
        } else {
            CP_WAIT(0);
        }
        __syncthreads();

        const uint32_t abuf = sa[it & 1];
        const uint32_t bbuf = sb[it & 1];

#pragma unroll
        for (int kk = 0; kk < BK; kk += 16) {
            uint32_t a[2][4];
#pragma unroll
            for (int mi = 0; mi < 2; mi++) {
                uint32_t addr = abuf + SW128((a_mr + mi * 16) * 128 + (kk + a_koff) * 2);
                LDSM_X4(a[mi], addr);
            }
#pragma unroll
            for (int j2 = 0; j2 < NFRAG / 2; j2++) {
                uint32_t b[4];
                uint32_t addr = bbuf + SW128((b_nr + j2 * 16) * 128 + (kk + b_koff) * 2);
                LDSM_X4(b, addr);
                mma_f16(acc[0][2 * j2],     a[0], b[0], b[1]);
                mma_f16(acc[1][2 * j2],     a[1], b[0], b[1]);
                mma_f16(acc[0][2 * j2 + 1], a[0], b[2], b[3]);
                mma_f16(acc[1][2 * j2 + 1], a[1], b[2], b[3]);
            }
        }
        __syncthreads();
    }

#pragma unroll
    for (int mi = 0; mi < 2; mi++) {
        int row = m0 + wm * 32 + mi * 16 + g;
#pragma unroll
        for (int j = 0; j < NFRAG; j++) {
            int col = wn * WN + 8 * j + q * 2;
            if (row < M)
                *reinterpret_cast<uint32_t*>(C + (size_t)row * BN + col) =
                    pack_h2(acc[mi][j][0], acc[mi][j][1]);
            if (row + 8 < M)
                *reinterpret_cast<uint32_t*>(C + (size_t)(row + 8) * BN + col) =
                    pack_h2(acc[mi][j][2], acc[mi][j][3]);
        }
    }
}

// ---------------------------------------------------------------------------
// CSR aggregation: warp per destination node, dual accumulator chains.
// res[d] = dinv[d]^2*h[d] + sum_e w_e*h[src_e] + bias ; ReLU -> fp16 out
// ---------------------------------------------------------------------------
__global__ void agg_csr_f128_h(const __half* __restrict__ h, const int2* __restrict__ csr,
                               const int* __restrict__ rowptr, const float* __restrict__ dinv,
                               const float* __restrict__ bias, __half* __restrict__ out,
                               int n, int e_cnt) {
    int warp = (blockIdx.x * blockDim.x + threadIdx.x) >> 5;
    int lane = threadIdx.x & 31;
    if (warp >= n) return;
    const int d = warp;

    float di = __ldg(dinv + d);
    di *= di;
    uint2 hv = __ldg(reinterpret_cast<const uint2*>(h + (size_t)d * 128) + lane);
    float2 h0 = __half22float2(*reinterpret_cast<__half2*>(&hv.x));
    float2 h1 = __half22float2(*reinterpret_cast<__half2*>(&hv.y));
    float4 b4 = __ldg(reinterpret_cast<const float4*>(bias) + lane);
    float4 acc0, acc1 = make_float4(0.f, 0.f, 0.f, 0.f);
    acc0.x = h0.x * di + b4.x;
    acc0.y = h0.y * di + b4.y;
    acc0.z = h1.x * di + b4.z;
    acc0.w = h1.y * di + b4.w;

    int start = __ldg(rowptr + d);
    int end   = (d == n - 1) ? e_cnt : __ldg(rowptr + d + 1);

    for (int base = start; base < end; base += 32) {
        int m = min(32, end - base);
        int2 ew = make_int2(0, 0);
        if (lane < m) ew = __ldg(csr + base + lane);
        int j = 0;
        for (; j + 1 < m; j += 2) {
            int   s0 = __shfl_sync(0xffffffffu, ew.x, j);
            float w0 = __int_as_float(__shfl_sync(0xffffffffu, ew.y, j));
            int   s1 = __shfl_sync(0xffffffffu, ew.x, j + 1);
            float w1 = __int_as_float(__shfl_sync(0xffffffffu, ew.y, j + 1));
            uint2 va = __ldg(reinterpret_cast<const uint2*>(h + (size_t)s0 * 128) + lane);
            uint2 vb = __ldg(reinterpret_cast<const uint2*>(h + (size_t)s1 * 128) + lane);
            float2 a0 = __half22float2(*reinterpret_cast<__half2*>(&va.x));
            float2 a1 = __half22float2(*reinterpret_cast<__half2*>(&va.y));
            float2 c0 = __half22float2(*reinterpret_cast<__half2*>(&vb.x));
            float2 c1 = __half22float2(*reinterpret_cast<__half2*>(&vb.y));
            acc0.x = fmaf(w0, a0.x, acc0.x);
            acc0.y = fmaf(w0, a0.y, acc0.y);
            acc0.z = fmaf(w0, a1.x, acc0.z);
            acc0.w = fmaf(w0, a1.y, acc0.w);
            acc1.x = fmaf(w1, c0.x, acc1.x);
            acc1.y = fmaf(w1, c0.y, acc1.y);
            acc1.z = fmaf(w1, c1.x, acc1.z);
            acc1.w = fmaf(w1, c1.y, acc1.w);
        }
        if (j < m) {
            int   s0 = __shfl_sync(0xffffffffu, ew.x, j);
            float w0 = __int_as_float(__shfl_sync(0xffffffffu, ew.y, j));
            uint2 va = __ldg(reinterpret_cast<const uint2*>(h + (size_t)s0 * 128) + lane);
            float2 a0 = __half22float2(*reinterpret_cast<__half2*>(&va.x));
            float2 a1 = __half22float2(*reinterpret_cast<__half2*>(&va.y));
            acc0.x = fmaf(w0, a0.x, acc0.x);
            acc0.y = fmaf(w0, a0.y, acc0.y);
            acc0.z = fmaf(w0, a1.x, acc0.z);
            acc0.w = fmaf(w0, a1.y, acc0.w);
        }
    }
    acc0.x = fmaxf(acc0.x + acc1.x, 0.f);
    acc0.y = fmaxf(acc0.y + acc1.y, 0.f);
    acc0.z = fmaxf(acc0.z + acc1.z, 0.f);
    acc0.w = fmaxf(acc0.w + acc1.w, 0.f);
    uint2 o;
    o.x = pack_h2(acc0.x, acc0.y);
    o.y = pack_h2(acc0.z, acc0.w);
    *(reinterpret_cast<uint2*>(out + (size_t)d * 128) + lane) = o;
}

// Final layer: F=64, no ReLU, fp32 output
__global__ void agg_csr_f64_out(const __half* __restrict__ h, const int2* __restrict__ csr,
                                const int* __restrict__ rowptr, const float* __restrict__ dinv,
                                const float* __restrict__ bias, float* __restrict__ out,
                                int n, int e_cnt) {
    int warp = (blockIdx.x * blockDim.x + threadIdx.x) >> 5;
    int lane = threadIdx.x & 31;
    if (warp >= n) return;
    const int d = warp;

    float di = __ldg(dinv + d);
    di *= di;
    uint32_t hv = __ldg(reinterpret_cast<const uint32_t*>(h + (size_t)d * 64) + lane);
    float2 h0 = __half22float2(*reinterpret_cast<__half2*>(&hv));
    float2 b2 = __ldg(reinterpret_cast<const float2*>(bias) + lane);
    float2 acc0, acc1 = make_float2(0.f, 0.f);
    acc0.x = h0.x * di + b2.x;
    acc0.y = h0.y * di + b2.y;

    int start = __ldg(rowptr + d);
    int end   = (d == n - 1) ? e_cnt : __ldg(rowptr + d + 1);

    for (int base = start; base < end; base += 32) {
        int m = min(32, end - base);
        int2 ew = make_int2(0, 0);
        if (lane < m) ew = __ldg(csr + base + lane);
        int j = 0;
        for (; j + 1 < m; j += 2) {
            int   s0 = __shfl_sync(0xffffffffu, ew.x, j);
            float w0 = __int_as_float(__shfl_sync(0xffffffffu, ew.y, j));
            int   s1 = __shfl_sync(0xffffffffu, ew.x, j + 1);
            float w1 = __int_as_float(__shfl_sync(0xffffffffu, ew.y, j + 1));
            uint32_t va = __ldg(reinterpret_cast<const uint32_t*>(h + (size_t)s0 * 64) + lane);
            uint32_t vb = __ldg(reinterpret_cast<const uint32_t*>(h + (size_t)s1 * 64) + lane);
            float2 a0 = __half22float2(*reinterpret_cast<__half2*>(&va));
            float2 c0 = __half22float2(*reinterpret_cast<__half2*>(&vb));
            acc0.x = fmaf(w0, a0.x, acc0.x);
            acc0.y = fmaf(w0, a0.y, acc0.y);
            acc1.x = fmaf(w1, c0.x, acc1.x);
            acc1.y = fmaf(w1, c0.y, acc1.y);
        }
        if (j < m) {
            int   s0 = __shfl_sync(0xffffffffu, ew.x, j);
            float w0 = __int_as_float(__shfl_sync(0xffffffffu, ew.y, j));
            uint32_t va = __ldg(reinterpret_cast<const uint32_t*>(h + (size_t)s0 * 64) + lane);
            float2 a0 = __half22float2(*reinterpret_cast<__half2*>(&va));
            acc0.x = fmaf(w0, a0.x, acc0.x);
            acc0.y = fmaf(w0, a0.y, acc0.y);
        }
    }
    *(reinterpret_cast<float2*>(out + (size_t)d * 64) + lane) =
        make_float2(acc0.x + acc1.x, acc0.y + acc1.y);
}

// ---------------------------------------------------------------------------
// Launcher — order chosen so gemm_hmma<256,128> is launch #4 (ncu capture slot)
// ---------------------------------------------------------------------------
extern "C" void kernel_launch(void* const* d_in, const int* in_sizes, int n_in,
                              void* d_out, int out_size) {
    const float* x   = (const float*)d_in[0];
    const int*   ei  = (const int*)d_in[1];     // int32 edge_index [2, E]
    const float* W1  = (const float*)d_in[2];
    const float* b1  = (const float*)d_in[3];
    const float* W2  = (const float*)d_in[4];
    const float* b2  = (const float*)d_in[5];
    const float* W3  = (const float*)d_in[6];
    const float* b3  = (const float*)d_in[7];
    float*       out = (float*)d_out;

    const int E = in_sizes[1] / 2;      // 1,600,000
    const int N = in_sizes[0] / FEAT;   // 100,000

    void *pX, *pA, *pB, *pC, *pW1, *pW2, *pW3;
    void *pDinv, *pDeg, *pRow, *pCur, *pBS, *pCsr;
    cudaGetSymbolAddress(&pX, g_hX);
    cudaGetSymbolAddress(&pA, g_hA);
    cudaGetSymbolAddress(&pB, g_hB);
    cudaGetSymbolAddress(&pC, g_hC);
    cudaGetSymbolAddress(&pW1, g_Wt1);
    cudaGetSymbolAddress(&pW2, g_Wt2);
    cudaGetSymbolAddress(&pW3, g_Wt3);
    cudaGetSymbolAddress(&pDinv, g_dinv);
    cudaGetSymbolAddress(&pDeg, g_deg);
    cudaGetSymbolAddress(&pRow, g_rowptr);
    cudaGetSymbolAddress(&pCur, g_cursor);
    cudaGetSymbolAddress(&pBS, g_blocksum);
    cudaGetSymbolAddress(&pCsr, g_csr);
    __half* hX    = (__half*)pX;
    __half* hA    = (__half*)pA;
    __half* hB    = (__half*)pB;
    __half* hC    = (__half*)pC;
    __half* Wt1   = (__half*)pW1;
    __half* Wt2   = (__half*)pW2;
    __half* Wt3   = (__half*)pW3;
    float* dinv   = (float*)pDinv;
    int*   deg    = (int*)pDeg;
    int*   rowptr = (int*)pRow;
    int*   cursor = (int*)pCur;
    int*   bsum   = (int*)pBS;
    int2*  csr    = (int2*)pCsr;

    const int T  = 256;
    const int gN = (N + T - 1) / T;
    const int gE = (E + T - 1) / T;
    const int gM = (N + 127) / 128;
    const int gW = ((size_t)N * 32 + T - 1) / T;
    const int gX = ((N * FEAT / 4) + T - 1) / T;

    const int smem128 = 2 * (16384 + 16384) + 1024;     // 66.5 KB
    const int smem64  = 2 * (16384 + 8192) + 1024;      // 50 KB

    static bool attr_done = false;
    if (!attr_done) {
        cudaFuncSetAttribute(gemm_hmma<256, 128>,
                             cudaFuncAttributeMaxDynamicSharedMemorySize, smem128);
        cudaFuncSetAttribute(gemm_hmma<128, 128>,
                             cudaFuncAttributeMaxDynamicSharedMemorySize, smem128);
        cudaFuncSetAttribute(gemm_hmma<128, 64>,
                             cudaFuncAttributeMaxDynamicSharedMemorySize, smem64);
        attr_done = true;
    }

    // ---- launches 1-4: preconvert then layer-1 GEMM (position 4 = ncu slot) ----
    k_x2h<<<gX, T>>>(x, hX, N * FEAT / 4);                         // 1
    k_w2h_t<<<(FEAT * HID + T - 1) / T, T>>>(W1, Wt1, FEAT, HID);  // 2
    k_w2h_t<<<(HID * HID + T - 1) / T, T>>>(W2, Wt2, HID, HID);    // 3
    gemm_hmma<256, 128><<<gM, 256, smem128>>>(hX, Wt1, hA, N);     // 4 <- profiled
    k_w2h_t<<<(HID * OUTF + T - 1) / T, T>>>(W3, Wt3, HID, OUTF);  // 5

    // ---- CSR prep (independent of gemm1, ordered before agg1) ----
    k_deg_init<<<gN, T>>>(deg, N);
    k_deg_count<<<gE, T>>>(ei, deg, E);
    k_scan_block<<<SCAN_NB, 256>>>(deg, rowptr, bsum, dinv, N);
    k_scan_mid<<<1, 512>>>(bsum, SCAN_NB);
    k_scan_add<<<gN, T>>>(rowptr, cursor, bsum, N);
    k_scatter<<<gE, T>>>(ei, dinv, cursor, csr, E);

    // ---- layer 1 agg ; layers 2-3 ----
    agg_csr_f128_h<<<gW, T>>>(hA, csr, rowptr, dinv, b1, hB, N, E);
    gemm_hmma<128, 128><<<gM, 256, smem128>>>(hB, Wt2, hA, N);
    agg_csr_f128_h<<<gW, T>>>(hA, csr, rowptr, dinv, b2, hB, N, E);
    gemm_hmma<128, 64><<<gM, 256, smem64>>>(hB, Wt3, hC, N);
    agg_csr_f64_out<<<gW, T>>>(hC, csr, rowptr, dinv, b3, out, N, E);
}